// round 11
// baseline (speedup 1.0000x reference)
#include <cuda_runtime.h>
#include <cuda_bf16.h>
#include <cstdint>
#include <math.h>

#define S_        8192
#define HID_      1280
#define H_        16
#define D_        80
#define C_        8
#define L_        1024
#define THREE_HID 3840

// ---------------------------------------------------------------------------
// Scratch (allocation-free rule: __device__ globals)
// ---------------------------------------------------------------------------
__device__ float g_qkv[(size_t)S_ * THREE_HID];
__device__ __nv_bfloat16 g_xhi[(size_t)S_ * HID_];
__device__ __nv_bfloat16 g_xlo[(size_t)S_ * HID_];
__device__ __nv_bfloat16 g_wqt_hi[(size_t)THREE_HID * HID_];  // Wqkv^T [N][K]
__device__ __nv_bfloat16 g_wqt_lo[(size_t)THREE_HID * HID_];
__device__ __nv_bfloat16 g_wpt_hi[(size_t)HID_ * HID_];       // Wproj^T [N][K]
__device__ __nv_bfloat16 g_wpt_lo[(size_t)HID_ * HID_];
__device__ __nv_bfloat16 g_ahi[(size_t)S_ * HID_];            // attn out hi/lo
__device__ __nv_bfloat16 g_alo[(size_t)S_ * HID_];
__device__ __nv_bfloat16 g_qhi[(size_t)H_ * S_ * D_];
__device__ __nv_bfloat16 g_qlo[(size_t)H_ * S_ * D_];
__device__ __nv_bfloat16 g_khi[(size_t)H_ * S_ * D_];
__device__ __nv_bfloat16 g_klo[(size_t)H_ * S_ * D_];
__device__ __nv_bfloat16 g_vhi[(size_t)H_ * S_ * D_];
__device__ __nv_bfloat16 g_vlo[(size_t)H_ * S_ * D_];

__device__ __forceinline__ uint32_t smem_u32(const void* p) {
    uint32_t a;
    asm("{ .reg .u64 t; cvta.to.shared.u64 t, %1; cvt.u32.u64 %0, t; }"
        : "=r"(a) : "l"(p));
    return a;
}
__device__ __forceinline__ uint32_t pk2(float lo, float hi) {
    uint32_t r;
    asm("cvt.rn.bf16x2.f32 %0, %1, %2;" : "=r"(r) : "f"(hi), "f"(lo));
    return r;
}
__device__ __forceinline__ float lo_of(uint32_t p) { return __uint_as_float(p << 16); }
__device__ __forceinline__ float hi_of(uint32_t p) { return __uint_as_float(p & 0xffff0000u); }

#define MMA4(cc, aa, b0, b1)                                                    \
    asm volatile("mma.sync.aligned.m16n8k16.row.col.f32.bf16.bf16.f32 "         \
                 "{%0,%1,%2,%3},{%4,%5,%6,%7},{%8,%9},{%0,%1,%2,%3};"           \
                 : "+f"((cc)[0]), "+f"((cc)[1]), "+f"((cc)[2]), "+f"((cc)[3])   \
                 : "r"((aa)[0]), "r"((aa)[1]), "r"((aa)[2]), "r"((aa)[3]),      \
                   "r"(b0), "r"(b1))
#define LDSM4(r, addr)                                                          \
    asm volatile("ldmatrix.sync.aligned.m8n8.x4.shared.b16 {%0,%1,%2,%3}, [%4];"\
                 : "=r"((r)[0]), "=r"((r)[1]), "=r"((r)[2]), "=r"((r)[3])       \
                 : "r"(addr))
#define LDSM4T(r, addr)                                                         \
    asm volatile("ldmatrix.sync.aligned.m8n8.x4.trans.shared.b16 {%0,%1,%2,%3}, [%4];" \
                 : "=r"((r)[0]), "=r"((r)[1]), "=r"((r)[2]), "=r"((r)[3])       \
                 : "r"(addr))
#define CPA16(dst, src)                                                         \
    asm volatile("cp.async.cg.shared.global [%0], [%1], 16;" :: "r"(dst), "l"(src))

// ---------------------------------------------------------------------------
// bf16-split conversion kernels
// ---------------------------------------------------------------------------
__global__ void split_rows(const float* __restrict__ in,
                           __nv_bfloat16* __restrict__ hi,
                           __nv_bfloat16* __restrict__ lo, int n)
{
    int i = blockIdx.x * blockDim.x + threadIdx.x;
    if (i >= n) return;
    float v = in[i];
    __nv_bfloat16 h = __float2bfloat16(v);
    hi[i] = h;
    lo[i] = __float2bfloat16(v - __bfloat162float(h));
}

__global__ void split_t(const float* __restrict__ W,
                        __nv_bfloat16* __restrict__ hi,
                        __nv_bfloat16* __restrict__ lo, int K, int N)
{
    __shared__ float t[32][33];
    int n0 = blockIdx.x * 32, k0 = blockIdx.y * 32;
    int tx = threadIdx.x, ty = threadIdx.y;   // (32, 8)
#pragma unroll
    for (int i = 0; i < 32; i += 8)
        t[ty + i][tx] = W[(size_t)(k0 + ty + i) * N + n0 + tx];
    __syncthreads();
#pragma unroll
    for (int i = 0; i < 32; i += 8) {
        float v = t[tx][ty + i];
        __nv_bfloat16 h = __float2bfloat16(v);
        size_t o = (size_t)(n0 + ty + i) * K + k0 + tx;
        hi[o] = h;
        lo[o] = __float2bfloat16(v - __bfloat162float(h));
    }
}

// ---------------------------------------------------------------------------
// Small-CTA bf16-split GEMM: C = A @ B^T + bias.
// 64(M) x 128(N) tile, BK=32, 128 threads (4 warps, warp tile 32x64),
// double-buffered cp.async, 3 CTAs/SM.
// R11: term-major MMA order (all Ah*Bh, then Ah*Bl, then Al*Bh) so
// dependent reuses of each accumulator are 16 MMAs apart.
// ---------------------------------------------------------------------------
#define AST 40
#define A64_BYTES (64 * AST * 2)           // 5120
#define B128_BYTES (128 * AST * 2)         // 10240
#define STAGE_SM (2 * A64_BYTES + 2 * B128_BYTES)   // 30720
#define GEMM_SM_SMEM_BYTES (2 * STAGE_SM)           // 61440

__global__ __launch_bounds__(128, 3) void mma_gemm_bias_sm(
    const __nv_bfloat16* __restrict__ Ahi, const __nv_bfloat16* __restrict__ Alo,
    const __nv_bfloat16* __restrict__ Bhi, const __nv_bfloat16* __restrict__ Blo,
    const float* __restrict__ bias, float* __restrict__ Cm,
    int M, int N, int K)
{
    extern __shared__ __nv_bfloat16 smb[];
    const uint32_t sb = smem_u32(smb);

    const int tid  = threadIdx.x;
    const int lane = tid & 31, warp = tid >> 5;   // 0..3
    const int warpM = warp & 1;
    const int warpN = warp >> 1;
    const int quad = lane >> 3, l8 = lane & 7;
    const int tileN = blockIdx.x, tileM = blockIdx.y;

    const __nv_bfloat16* gAh = Ahi + (size_t)(tileM * 64) * K;
    const __nv_bfloat16* gAl = Alo + (size_t)(tileM * 64) * K;
    const __nv_bfloat16* gBh = Bhi + (size_t)(tileN * 128) * K;
    const __nv_bfloat16* gBl = Blo + (size_t)(tileN * 128) * K;

    float c[2][8][4];
#pragma unroll
    for (int mi = 0; mi < 2; mi++)
#pragma unroll
        for (int nt = 0; nt < 8; nt++)
#pragma unroll
            for (int r = 0; r < 4; r++) c[mi][nt][r] = 0.f;

    const int nch = K >> 5;

    auto issue = [&](int ch, int buf) {
        const int k0 = ch * 32;
        const uint32_t base = sb + (uint32_t)(buf * STAGE_SM);
#pragma unroll
        for (int p = 0; p < 2; p++) {    // A: 64 rows x 4 segs
            int idx = tid + p * 128;
            int row = idx >> 2, seg = idx & 3;
            uint32_t so = (uint32_t)((row * AST + seg * 8) * 2);
            size_t go = (size_t)row * K + k0 + seg * 8;
            CPA16(base + so,             gAh + go);
            CPA16(base + A64_BYTES + so, gAl + go);
        }
#pragma unroll
        for (int p = 0; p < 4; p++) {    // B: 128 rows x 4 segs
            int idx = tid + p * 128;
            int row = idx >> 2, seg = idx & 3;
            uint32_t so = (uint32_t)((row * AST + seg * 8) * 2);
            size_t go = (size_t)row * K + k0 + seg * 8;
            CPA16(base + 2 * A64_BYTES + so,              gBh + go);
            CPA16(base + 2 * A64_BYTES + B128_BYTES + so, gBl + go);
        }
        asm volatile("cp.async.commit_group;" ::: "memory");
    };

    issue(0, 0);

    for (int ch = 0; ch < nch; ch++) {
        if (ch + 1 < nch) {
            issue(ch + 1, (ch + 1) & 1);
            asm volatile("cp.async.wait_group 1;" ::: "memory");
        } else {
            asm volatile("cp.async.wait_group 0;" ::: "memory");
        }
        __syncthreads();

        const uint32_t base = sb + (uint32_t)((ch & 1) * STAGE_SM);
        const uint32_t aHb = base;
        const uint32_t aLb = base + A64_BYTES;
        const uint32_t bHb = base + 2 * A64_BYTES;
        const uint32_t bLb = base + 2 * A64_BYTES + B128_BYTES;

#pragma unroll
        for (int s = 0; s < 2; s++) {
            uint32_t ah[2][4], al[2][4], bh[4][4], bl[4][4];
#pragma unroll
            for (int mi = 0; mi < 2; mi++) {
                int row = warpM * 32 + mi * 16 + (quad & 1) * 8 + l8;
                int ke  = s * 16 + (quad >> 1) * 8;
                LDSM4(ah[mi], aHb + (uint32_t)((row * AST + ke) * 2));
                LDSM4(al[mi], aLb + (uint32_t)((row * AST + ke) * 2));
            }
#pragma unroll
            for (int nj = 0; nj < 4; nj++) {
                int nrow = warpN * 64 + nj * 16 + (quad >> 1) * 8 + l8;
                int ke   = s * 16 + (quad & 1) * 8;
                LDSM4(bh[nj], bHb + (uint32_t)((nrow * AST + ke) * 2));
                LDSM4(bl[nj], bLb + (uint32_t)((nrow * AST + ke) * 2));
            }
            // term-major: 16 independent accumulators between dependent reuses
#pragma unroll
            for (int mi = 0; mi < 2; mi++)
#pragma unroll
                for (int nt = 0; nt < 8; nt++) {
                    int nj = nt >> 1, hh = (nt & 1) * 2;
                    MMA4(c[mi][nt], ah[mi], bh[nj][hh], bh[nj][hh + 1]);
                }
#pragma unroll
            for (int mi = 0; mi < 2; mi++)
#pragma unroll
                for (int nt = 0; nt < 8; nt++) {
                    int nj = nt >> 1, hh = (nt & 1) * 2;
                    MMA4(c[mi][nt], ah[mi], bl[nj][hh], bl[nj][hh + 1]);
                }
#pragma unroll
            for (int mi = 0; mi < 2; mi++)
#pragma unroll
                for (int nt = 0; nt < 8; nt++) {
                    int nj = nt >> 1, hh = (nt & 1) * 2;
                    MMA4(c[mi][nt], al[mi], bh[nj][hh], bh[nj][hh + 1]);
                }
        }
        __syncthreads();
    }

    const int m0 = tileM * 64 + warpM * 32;
    const int n0 = tileN * 128 + warpN * 64;
    const int rq = lane >> 2, cq = (lane & 3) * 2;
#pragma unroll
    for (int mi = 0; mi < 2; mi++) {
#pragma unroll
        for (int nt = 0; nt < 8; nt++) {
            int col = n0 + nt * 8 + cq;
            float2 b2 = *(const float2*)(bias + col);
            int r0 = m0 + mi * 16 + rq;
            float2 o0, o1;
            o0.x = c[mi][nt][0] + b2.x; o0.y = c[mi][nt][1] + b2.y;
            o1.x = c[mi][nt][2] + b2.x; o1.y = c[mi][nt][3] + b2.y;
            *(float2*)(Cm + (size_t)r0 * N + col)       = o0;
            *(float2*)(Cm + (size_t)(r0 + 8) * N + col) = o1;
        }
    }
}

// ---------------------------------------------------------------------------
// RoPE + split: qkv[S,3*HID] -> bf16 hi/lo Q (pre-scaled), K, V in [H][S][D]
// ---------------------------------------------------------------------------
__global__ void rope_split(const float* __restrict__ cosp,
                           const float* __restrict__ sinp)
{
    int idx = blockIdx.x * blockDim.x + threadIdx.x;
    if (idx >= S_ * HID_) return;
    int s   = idx / HID_;
    int col = idx - s * HID_;
    int h   = col / D_;
    int d   = col - h * D_;

    const float* base = g_qkv + (size_t)s * THREE_HID;
    float qv = base[col];
    float kv = base[HID_ + col];
    float vv = base[2 * HID_ + col];

    float cc = cosp[s * D_ + d];
    float sn = sinp[s * D_ + d];

    int off = (d < 40) ? (col + 40) : (col - 40);
    float sgn = (d < 40) ? -1.f : 1.f;
    float qrot = sgn * base[off];
    float krot = sgn * base[HID_ + off];

    const float inv_scale = rsqrtf((float)D_);
    float qf = (qv * cc + qrot * sn) * inv_scale;
    float kf = kv * cc + krot * sn;

    size_t o = (size_t)h * S_ * D_ + (size_t)s * D_ + d;
    __nv_bfloat16 qh = __float2bfloat16(qf);
    __nv_bfloat16 kh = __float2bfloat16(kf);
    __nv_bfloat16 vh = __float2bfloat16(vv);
    g_qhi[o] = qh; g_qlo[o] = __float2bfloat16(qf - __bfloat162float(qh));
    g_khi[o] = kh; g_klo[o] = __float2bfloat16(kf - __bfloat162float(kh));
    g_vhi[o] = vh; g_vlo[o] = __float2bfloat16(vv - __bfloat162float(vh));
}

// ---------------------------------------------------------------------------
// HMMA flash attention. 64 q-rows/CTA, 64k tiles, 4 warps, 2 CTAs/SM.
// R11: term-major QK order; PV alternates even/odd accumulators.
// ---------------------------------------------------------------------------
#define ATT_STRIDE 88
#define Q_BYTES (64 * ATT_STRIDE * 2)     // 11264
#define T_BYTES (64 * ATT_STRIDE * 2)     // 11264
#define OFF_QH 0
#define OFF_QL Q_BYTES
#define OFF_KH (2 * Q_BYTES)
#define OFF_KL (2 * Q_BYTES + 2 * T_BYTES)
#define OFF_VH (2 * Q_BYTES + 4 * T_BYTES)
#define OFF_VL (2 * Q_BYTES + 6 * T_BYTES)
#define ATTN_SMEM_BYTES (2 * Q_BYTES + 8 * T_BYTES)   // 112640

__global__ __launch_bounds__(128, 2) void attn_mma()
{
    extern __shared__ char smc[];
    const uint32_t sb = smem_u32(smc);

    const int bx = blockIdx.x;
    const int qt = bx & 15;           // 16 q-tiles of 64 rows
    const int h  = (bx >> 4) & 15;
    const int c  = bx >> 8;

    const int tid = threadIdx.x;
    const int lane = tid & 31, w = tid >> 5;   // w: 0..3
    const int quad = lane >> 3, l8 = lane & 7;

    const size_t hq = (size_t)h * S_ * D_ + (size_t)(c * L_ + qt * 64) * D_;
    const size_t hk = (size_t)h * S_ * D_ + (size_t)(c * L_) * D_;

    for (int i = tid; i < 640; i += 128) {
        int row = i / 10, seg = i - row * 10;
        uint32_t off = (uint32_t)(row * ATT_STRIDE + seg * 8) * 2;
        size_t g = hq + (size_t)row * 80 + seg * 8;
        CPA16(sb + OFF_QH + off, g_qhi + g);
        CPA16(sb + OFF_QL + off, g_qlo + g);
    }
    for (int i = tid; i < 640; i += 128) {
        int row = i / 10, seg = i - row * 10;
        uint32_t off = (uint32_t)(row * ATT_STRIDE + seg * 8) * 2;
        size_t g = hk + (size_t)row * 80 + seg * 8;
        CPA16(sb + OFF_KH + off, g_khi + g);
        CPA16(sb + OFF_KL + off, g_klo + g);
        CPA16(sb + OFF_VH + off, g_vhi + g);
        CPA16(sb + OFF_VL + off, g_vlo + g);
    }
    asm volatile("cp.async.commit_group;" ::: "memory");

    float m_a = -1e30f, m_b = -1e30f, l_a = 0.f, l_b = 0.f;
    float out[10][4];
#pragma unroll
    for (int vt = 0; vt < 10; vt++)
#pragma unroll
        for (int r = 0; r < 4; r++) out[vt][r] = 0.f;

    for (int t = 0; t < 16; t++) {
        if (t + 1 < 16) {
            const uint32_t s1 = ((t + 1) & 1) * T_BYTES;
            const size_t tb = hk + (size_t)(t + 1) * 64 * 80;
            for (int i = tid; i < 640; i += 128) {
                int row = i / 10, seg = i - row * 10;
                uint32_t off = (uint32_t)(row * ATT_STRIDE + seg * 8) * 2 + s1;
                size_t g = tb + (size_t)row * 80 + seg * 8;
                CPA16(sb + OFF_KH + off, g_khi + g);
                CPA16(sb + OFF_KL + off, g_klo + g);
                CPA16(sb + OFF_VH + off, g_vhi + g);
                CPA16(sb + OFF_VL + off, g_vlo + g);
            }
            asm volatile("cp.async.commit_group;" ::: "memory");
            asm volatile("cp.async.wait_group 1;" ::: "memory");
        } else {
            asm volatile("cp.async.wait_group 0;" ::: "memory");
        }
        __syncthreads();

        const uint32_t stg = (t & 1) * T_BYTES;
        const uint32_t KHs = sb + OFF_KH + stg;
        const uint32_t KLs = sb + OFF_KL + stg;
        const uint32_t VHs = sb + OFF_VH + stg;
        const uint32_t VLs = sb + OFF_VL + stg;

        float sc[8][4];
#pragma unroll
        for (int nt = 0; nt < 8; nt++)
#pragma unroll
            for (int r = 0; r < 4; r++) sc[nt][r] = 0.f;

        const int arow = w * 16 + (quad & 1) * 8 + l8;
#pragma unroll
        for (int kk = 0; kk < 5; kk++) {
            uint32_t ah[4], al[4], bh[4][4], bl[4][4];
            uint32_t aoff = (uint32_t)(arow * ATT_STRIDE + kk * 16 + (quad >> 1) * 8) * 2;
            LDSM4(ah, sb + OFF_QH + aoff);
            LDSM4(al, sb + OFF_QL + aoff);
#pragma unroll
            for (int nj = 0; nj < 4; nj++) {
                uint32_t boff = (uint32_t)((nj * 16 + (quad >> 1) * 8 + l8) * ATT_STRIDE
                                           + kk * 16 + (quad & 1) * 8) * 2;
                LDSM4(bh[nj], KHs + boff);
                LDSM4(bl[nj], KLs + boff);
            }
            // term-major: 8 independent accumulators between reuses
#pragma unroll
            for (int nj = 0; nj < 4; nj++) {
                MMA4(sc[2 * nj],     ah, bh[nj][0], bh[nj][1]);
                MMA4(sc[2 * nj + 1], ah, bh[nj][2], bh[nj][3]);
            }
#pragma unroll
            for (int nj = 0; nj < 4; nj++) {
                MMA4(sc[2 * nj],     ah, bl[nj][0], bl[nj][1]);
                MMA4(sc[2 * nj + 1], ah, bl[nj][2], bl[nj][3]);
            }
#pragma unroll
            for (int nj = 0; nj < 4; nj++) {
                MMA4(sc[2 * nj],     al, bh[nj][0], bh[nj][1]);
                MMA4(sc[2 * nj + 1], al, bh[nj][2], bh[nj][3]);
            }
        }

        float mxa = sc[0][0], mxb = sc[0][2];
#pragma unroll
        for (int nt = 0; nt < 8; nt++) {
            mxa = fmaxf(mxa, fmaxf(sc[nt][0], sc[nt][1]));
            mxb = fmaxf(mxb, fmaxf(sc[nt][2], sc[nt][3]));
        }
        mxa = fmaxf(mxa, __shfl_xor_sync(0xffffffffu, mxa, 1));
        mxa = fmaxf(mxa, __shfl_xor_sync(0xffffffffu, mxa, 2));
        mxb = fmaxf(mxb, __shfl_xor_sync(0xffffffffu, mxb, 1));
        mxb = fmaxf(mxb, __shfl_xor_sync(0xffffffffu, mxb, 2));
        float nma = fmaxf(m_a, mxa), nmb = fmaxf(m_b, mxb);
        float ca  = __expf(m_a - nma), cb = __expf(m_b - nmb);
        m_a = nma; m_b = nmb;

        float sa = 0.f, sbv = 0.f;
#pragma unroll
        for (int nt = 0; nt < 8; nt++) {
            sc[nt][0] = __expf(sc[nt][0] - m_a);
            sc[nt][1] = __expf(sc[nt][1] - m_a);
            sc[nt][2] = __expf(sc[nt][2] - m_b);
            sc[nt][3] = __expf(sc[nt][3] - m_b);
            sa  += sc[nt][0] + sc[nt][1];
            sbv += sc[nt][2] + sc[nt][3];
        }
        sa  += __shfl_xor_sync(0xffffffffu, sa, 1);
        sa  += __shfl_xor_sync(0xffffffffu, sa, 2);
        sbv += __shfl_xor_sync(0xffffffffu, sbv, 1);
        sbv += __shfl_xor_sync(0xffffffffu, sbv, 2);
        l_a = l_a * ca + sa;
        l_b = l_b * cb + sbv;

        uint32_t Ph[4][4], Pl[4][4];
#pragma unroll
        for (int kk = 0; kk < 4; kk++) {
#pragma unroll
            for (int half = 0; half < 2; half++) {
                int nt = 2 * kk + half;
                uint32_t h0 = pk2(sc[nt][0], sc[nt][1]);
                uint32_t h1 = pk2(sc[nt][2], sc[nt][3]);
                Ph[kk][2 * half + 0] = h0;
                Ph[kk][2 * half + 1] = h1;
                Pl[kk][2 * half + 0] = pk2(sc[nt][0] - lo_of(h0), sc[nt][1] - hi_of(h0));
                Pl[kk][2 * half + 1] = pk2(sc[nt][2] - lo_of(h1), sc[nt][3] - hi_of(h1));
            }
        }

#pragma unroll
        for (int vt = 0; vt < 10; vt++) {
            out[vt][0] *= ca; out[vt][1] *= ca;
            out[vt][2] *= cb; out[vt][3] *= cb;
        }

        // PV: alternate even/odd output accumulators (dep distance 2)
#pragma unroll
        for (int kk = 0; kk < 4; kk++) {
#pragma unroll
            for (int vj = 0; vj < 5; vj++) {
                uint32_t vhf[4], vlf[4];
                uint32_t voff = (uint32_t)((kk * 16 + (quad & 1) * 8 + l8) * ATT_STRIDE
                                           + vj * 16 + (quad >> 1) * 8) * 2;
                LDSM4T(vhf, VHs + voff);
                LDSM4T(vlf, VLs + voff);
                MMA4(out[2 * vj],     Ph[kk], vhf[0], vhf[1]);
                MMA4(out[2 * vj + 1], Ph[kk], vhf[2], vhf[3]);
                MMA4(out[2 * vj],     Ph[kk], vlf[0], vlf[1]);
                MMA4(out[2 * vj + 1], Ph[kk], vlf[2], vlf[3]);
                MMA4(out[2 * vj],     Pl[kk], vhf[0], vhf[1]);
                MMA4(out[2 * vj + 1], Pl[kk], vhf[2], vhf[3]);
            }
        }
        __syncthreads();
    }

    float ila = 1.f / l_a, ilb = 1.f / l_b;
    int ra = c * L_ + qt * 64 + w * 16 + (lane >> 2);
    int colb = h * D_ + (lane & 3) * 2;
#pragma unroll
    for (int vt = 0; vt < 10; vt++) {
        int col = colb + vt * 8;
        float v0 = out[vt][0] * ila, v1 = out[vt][1] * ila;
        uint32_t hp = pk2(v0, v1);
        uint32_t lp = pk2(v0 - lo_of(hp), v1 - hi_of(hp));
        *(uint32_t*)(g_ahi + (size_t)ra * HID_ + col) = hp;
        *(uint32_t*)(g_alo + (size_t)ra * HID_ + col) = lp;
        float v2 = out[vt][2] * ilb, v3 = out[vt][3] * ilb;
        hp = pk2(v2, v3);
        lp = pk2(v2 - lo_of(hp), v3 - hi_of(hp));
        *(uint32_t*)(g_ahi + (size_t)(ra + 8) * HID_ + col) = hp;
        *(uint32_t*)(g_alo + (size_t)(ra + 8) * HID_ + col) = lp;
    }
}

// ---------------------------------------------------------------------------
// Launch pipeline
// ---------------------------------------------------------------------------
extern "C" void kernel_launch(void* const* d_in, const int* in_sizes, int n_in,
                              void* d_out, int out_size)
{
    const float* x     = (const float*)d_in[0];
    const float* cosp  = (const float*)d_in[1];
    const float* sinp  = (const float*)d_in[2];
    const float* Wqkv  = (const float*)d_in[3];
    const float* bqkv  = (const float*)d_in[4];
    const float* Wproj = (const float*)d_in[5];
    const float* bproj = (const float*)d_in[6];
    float* out = (float*)d_out;

    float* qkv_p;
    __nv_bfloat16 *xhi, *xlo, *wqh, *wql, *wph, *wpl, *ahi, *alo;
    cudaGetSymbolAddress((void**)&qkv_p, g_qkv);
    cudaGetSymbolAddress((void**)&xhi, g_xhi);
    cudaGetSymbolAddress((void**)&xlo, g_xlo);
    cudaGetSymbolAddress((void**)&wqh, g_wqt_hi);
    cudaGetSymbolAddress((void**)&wql, g_wqt_lo);
    cudaGetSymbolAddress((void**)&wph, g_wpt_hi);
    cudaGetSymbolAddress((void**)&wpl, g_wpt_lo);
    cudaGetSymbolAddress((void**)&ahi, g_ahi);
    cudaGetSymbolAddress((void**)&alo, g_alo);

    static int attr_set = 0;
    if (!attr_set) {
        cudaFuncSetAttribute(attn_mma,
                             cudaFuncAttributeMaxDynamicSharedMemorySize,
                             ATTN_SMEM_BYTES);
        cudaFuncSetAttribute(mma_gemm_bias_sm,
                             cudaFuncAttributeMaxDynamicSharedMemorySize,
                             GEMM_SM_SMEM_BYTES);
        attr_set = 1;
    }

    split_rows<<<(S_ * HID_ + 255) / 256, 256>>>(x, xhi, xlo, S_ * HID_);
    split_t<<<dim3(THREE_HID / 32, HID_ / 32), dim3(32, 8)>>>(Wqkv, wqh, wql, HID_, THREE_HID);
    split_t<<<dim3(HID_ / 32, HID_ / 32), dim3(32, 8)>>>(Wproj, wph, wpl, HID_, HID_);

    mma_gemm_bias_sm<<<dim3(THREE_HID / 128, S_ / 64), 128, GEMM_SM_SMEM_BYTES>>>(
        xhi, xlo, wqh, wql, bqkv, qkv_p, S_, THREE_HID, HID_);

    rope_split<<<(S_ * HID_ + 255) / 256, 256>>>(cosp, sinp);

    attn_mma<<<C_ * H_ * (L_ / 64), 128, ATTN_SMEM_BYTES>>>();

    mma_gemm_bias_sm<<<dim3(HID_ / 128, S_ / 64), 128, GEMM_SM_SMEM_BYTES>>>(
        ahi, alo, wph, wpl, bproj, out, S_, HID_, HID_);
}

// round 12
// speedup vs baseline: 1.0246x; 1.0246x over previous
#include <cuda_runtime.h>
#include <cuda_bf16.h>
#include <cstdint>
#include <math.h>

#define S_        8192
#define HID_      1280
#define H_        16
#define D_        80
#define C_        8
#define L_        1024
#define THREE_HID 3840

// ---------------------------------------------------------------------------
// Scratch (allocation-free rule: __device__ globals)
// ---------------------------------------------------------------------------
__device__ float g_qkv[(size_t)S_ * THREE_HID];
__device__ __nv_bfloat16 g_xhi[(size_t)S_ * HID_];
__device__ __nv_bfloat16 g_xlo[(size_t)S_ * HID_];
__device__ __nv_bfloat16 g_wqt_hi[(size_t)THREE_HID * HID_];  // Wqkv^T [N][K]
__device__ __nv_bfloat16 g_wqt_lo[(size_t)THREE_HID * HID_];
__device__ __nv_bfloat16 g_wpt_hi[(size_t)HID_ * HID_];       // Wproj^T [N][K]
__device__ __nv_bfloat16 g_wpt_lo[(size_t)HID_ * HID_];
__device__ __nv_bfloat16 g_ahi[(size_t)S_ * HID_];            // attn out hi/lo
__device__ __nv_bfloat16 g_alo[(size_t)S_ * HID_];
__device__ __nv_bfloat16 g_qhi[(size_t)H_ * S_ * D_];
__device__ __nv_bfloat16 g_qlo[(size_t)H_ * S_ * D_];
__device__ __nv_bfloat16 g_khi[(size_t)H_ * S_ * D_];
__device__ __nv_bfloat16 g_klo[(size_t)H_ * S_ * D_];
__device__ __nv_bfloat16 g_vhi[(size_t)H_ * S_ * D_];
__device__ __nv_bfloat16 g_vlo[(size_t)H_ * S_ * D_];

__device__ __forceinline__ uint32_t smem_u32(const void* p) {
    uint32_t a;
    asm("{ .reg .u64 t; cvta.to.shared.u64 t, %1; cvt.u32.u64 %0, t; }"
        : "=r"(a) : "l"(p));
    return a;
}
__device__ __forceinline__ uint32_t pk2(float lo, float hi) {
    uint32_t r;
    asm("cvt.rn.bf16x2.f32 %0, %1, %2;" : "=r"(r) : "f"(hi), "f"(lo));
    return r;
}
__device__ __forceinline__ float lo_of(uint32_t p) { return __uint_as_float(p << 16); }
__device__ __forceinline__ float hi_of(uint32_t p) { return __uint_as_float(p & 0xffff0000u); }

#define MMA4(cc, aa, b0, b1)                                                    \
    asm volatile("mma.sync.aligned.m16n8k16.row.col.f32.bf16.bf16.f32 "         \
                 "{%0,%1,%2,%3},{%4,%5,%6,%7},{%8,%9},{%0,%1,%2,%3};"           \
                 : "+f"((cc)[0]), "+f"((cc)[1]), "+f"((cc)[2]), "+f"((cc)[3])   \
                 : "r"((aa)[0]), "r"((aa)[1]), "r"((aa)[2]), "r"((aa)[3]),      \
                   "r"(b0), "r"(b1))
#define LDSM4(r, addr)                                                          \
    asm volatile("ldmatrix.sync.aligned.m8n8.x4.shared.b16 {%0,%1,%2,%3}, [%4];"\
                 : "=r"((r)[0]), "=r"((r)[1]), "=r"((r)[2]), "=r"((r)[3])       \
                 : "r"(addr))
#define LDSM4T(r, addr)                                                         \
    asm volatile("ldmatrix.sync.aligned.m8n8.x4.trans.shared.b16 {%0,%1,%2,%3}, [%4];" \
                 : "=r"((r)[0]), "=r"((r)[1]), "=r"((r)[2]), "=r"((r)[3])       \
                 : "r"(addr))
#define CPA16(dst, src)                                                         \
    asm volatile("cp.async.cg.shared.global [%0], [%1], 16;" :: "r"(dst), "l"(src))

// ---------------------------------------------------------------------------
// bf16-split conversion kernels (vectorized)
// ---------------------------------------------------------------------------
__global__ void split_rows(const float* __restrict__ in,
                           __nv_bfloat16* __restrict__ hi,
                           __nv_bfloat16* __restrict__ lo, int n4)
{
    int i = blockIdx.x * blockDim.x + threadIdx.x;
    if (i >= n4) return;
    float4 v = *(const float4*)(in + 4 * (size_t)i);
    uint32_t h01 = pk2(v.x, v.y);
    uint32_t h23 = pk2(v.z, v.w);
    uint32_t l01 = pk2(v.x - lo_of(h01), v.y - hi_of(h01));
    uint32_t l23 = pk2(v.z - lo_of(h23), v.w - hi_of(h23));
    uint2 hv; hv.x = h01; hv.y = h23;
    uint2 lv; lv.x = l01; lv.y = l23;
    *(uint2*)(hi + 4 * (size_t)i) = hv;
    *(uint2*)(lo + 4 * (size_t)i) = lv;
}

__global__ void split_t(const float* __restrict__ W,
                        __nv_bfloat16* __restrict__ hi,
                        __nv_bfloat16* __restrict__ lo, int K, int N)
{
    __shared__ float t[32][33];
    int n0 = blockIdx.x * 32, k0 = blockIdx.y * 32;
    int tx = threadIdx.x, ty = threadIdx.y;   // (32, 8)
#pragma unroll
    for (int i = 0; i < 32; i += 8)
        t[ty + i][tx] = W[(size_t)(k0 + ty + i) * N + n0 + tx];
    __syncthreads();
#pragma unroll
    for (int i = 0; i < 32; i += 8) {
        float v = t[tx][ty + i];
        __nv_bfloat16 h = __float2bfloat16(v);
        size_t o = (size_t)(n0 + ty + i) * K + k0 + tx;
        hi[o] = h;
        lo[o] = __float2bfloat16(v - __bfloat162float(h));
    }
}

// ---------------------------------------------------------------------------
// Small-CTA bf16-split GEMM: C = A @ B^T + bias.
// 64(M) x 128(N) tile, BK=32, 128 threads (4 warps, warp tile 32x64),
// double-buffered cp.async, 3 CTAs/SM.  3-term split.
// ---------------------------------------------------------------------------
#define AST 40
#define A64_BYTES (64 * AST * 2)           // 5120
#define B128_BYTES (128 * AST * 2)         // 10240
#define STAGE_SM (2 * A64_BYTES + 2 * B128_BYTES)   // 30720
#define GEMM_SM_SMEM_BYTES (2 * STAGE_SM)           // 61440

__global__ __launch_bounds__(128, 3) void mma_gemm_bias_sm(
    const __nv_bfloat16* __restrict__ Ahi, const __nv_bfloat16* __restrict__ Alo,
    const __nv_bfloat16* __restrict__ Bhi, const __nv_bfloat16* __restrict__ Blo,
    const float* __restrict__ bias, float* __restrict__ Cm,
    int M, int N, int K)
{
    extern __shared__ __nv_bfloat16 smb[];
    const uint32_t sb = smem_u32(smb);

    const int tid  = threadIdx.x;
    const int lane = tid & 31, warp = tid >> 5;   // 0..3
    const int warpM = warp & 1;
    const int warpN = warp >> 1;
    const int quad = lane >> 3, l8 = lane & 7;
    const int tileN = blockIdx.x, tileM = blockIdx.y;

    const __nv_bfloat16* gAh = Ahi + (size_t)(tileM * 64) * K;
    const __nv_bfloat16* gAl = Alo + (size_t)(tileM * 64) * K;
    const __nv_bfloat16* gBh = Bhi + (size_t)(tileN * 128) * K;
    const __nv_bfloat16* gBl = Blo + (size_t)(tileN * 128) * K;

    float c[2][8][4];
#pragma unroll
    for (int mi = 0; mi < 2; mi++)
#pragma unroll
        for (int nt = 0; nt < 8; nt++)
#pragma unroll
            for (int r = 0; r < 4; r++) c[mi][nt][r] = 0.f;

    const int nch = K >> 5;

    auto issue = [&](int ch, int buf) {
        const int k0 = ch * 32;
        const uint32_t base = sb + (uint32_t)(buf * STAGE_SM);
#pragma unroll
        for (int p = 0; p < 2; p++) {    // A: 64 rows x 4 segs
            int idx = tid + p * 128;
            int row = idx >> 2, seg = idx & 3;
            uint32_t so = (uint32_t)((row * AST + seg * 8) * 2);
            size_t go = (size_t)row * K + k0 + seg * 8;
            CPA16(base + so,             gAh + go);
            CPA16(base + A64_BYTES + so, gAl + go);
        }
#pragma unroll
        for (int p = 0; p < 4; p++) {    // B: 128 rows x 4 segs
            int idx = tid + p * 128;
            int row = idx >> 2, seg = idx & 3;
            uint32_t so = (uint32_t)((row * AST + seg * 8) * 2);
            size_t go = (size_t)row * K + k0 + seg * 8;
            CPA16(base + 2 * A64_BYTES + so,              gBh + go);
            CPA16(base + 2 * A64_BYTES + B128_BYTES + so, gBl + go);
        }
        asm volatile("cp.async.commit_group;" ::: "memory");
    };

    issue(0, 0);

    for (int ch = 0; ch < nch; ch++) {
        if (ch + 1 < nch) {
            issue(ch + 1, (ch + 1) & 1);
            asm volatile("cp.async.wait_group 1;" ::: "memory");
        } else {
            asm volatile("cp.async.wait_group 0;" ::: "memory");
        }
        __syncthreads();

        const uint32_t base = sb + (uint32_t)((ch & 1) * STAGE_SM);
        const uint32_t aHb = base;
        const uint32_t aLb = base + A64_BYTES;
        const uint32_t bHb = base + 2 * A64_BYTES;
        const uint32_t bLb = base + 2 * A64_BYTES + B128_BYTES;

#pragma unroll
        for (int s = 0; s < 2; s++) {
            uint32_t ah[2][4], al[2][4], bh[4][4], bl[4][4];
#pragma unroll
            for (int mi = 0; mi < 2; mi++) {
                int row = warpM * 32 + mi * 16 + (quad & 1) * 8 + l8;
                int ke  = s * 16 + (quad >> 1) * 8;
                LDSM4(ah[mi], aHb + (uint32_t)((row * AST + ke) * 2));
                LDSM4(al[mi], aLb + (uint32_t)((row * AST + ke) * 2));
            }
#pragma unroll
            for (int nj = 0; nj < 4; nj++) {
                int nrow = warpN * 64 + nj * 16 + (quad >> 1) * 8 + l8;
                int ke   = s * 16 + (quad & 1) * 8;
                LDSM4(bh[nj], bHb + (uint32_t)((nrow * AST + ke) * 2));
                LDSM4(bl[nj], bLb + (uint32_t)((nrow * AST + ke) * 2));
            }
#pragma unroll
            for (int mi = 0; mi < 2; mi++)
#pragma unroll
                for (int nt = 0; nt < 8; nt++) {
                    int nj = nt >> 1, hh = (nt & 1) * 2;
                    MMA4(c[mi][nt], ah[mi], bh[nj][hh], bh[nj][hh + 1]);
                }
#pragma unroll
            for (int mi = 0; mi < 2; mi++)
#pragma unroll
                for (int nt = 0; nt < 8; nt++) {
                    int nj = nt >> 1, hh = (nt & 1) * 2;
                    MMA4(c[mi][nt], ah[mi], bl[nj][hh], bl[nj][hh + 1]);
                }
#pragma unroll
            for (int mi = 0; mi < 2; mi++)
#pragma unroll
                for (int nt = 0; nt < 8; nt++) {
                    int nj = nt >> 1, hh = (nt & 1) * 2;
                    MMA4(c[mi][nt], al[mi], bh[nj][hh], bh[nj][hh + 1]);
                }
        }
        __syncthreads();
    }

    const int m0 = tileM * 64 + warpM * 32;
    const int n0 = tileN * 128 + warpN * 64;
    const int rq = lane >> 2, cq = (lane & 3) * 2;
#pragma unroll
    for (int mi = 0; mi < 2; mi++) {
#pragma unroll
        for (int nt = 0; nt < 8; nt++) {
            int col = n0 + nt * 8 + cq;
            float2 b2 = *(const float2*)(bias + col);
            int r0 = m0 + mi * 16 + rq;
            float2 o0, o1;
            o0.x = c[mi][nt][0] + b2.x; o0.y = c[mi][nt][1] + b2.y;
            o1.x = c[mi][nt][2] + b2.x; o1.y = c[mi][nt][3] + b2.y;
            *(float2*)(Cm + (size_t)r0 * N + col)       = o0;
            *(float2*)(Cm + (size_t)(r0 + 8) * N + col) = o1;
        }
    }
}

// ---------------------------------------------------------------------------
// RoPE + split (vectorized, 2 elems/thread):
// qkv[S,3*HID] -> bf16 hi/lo Q (pre-scaled), K, V in [H][S][D]
// ---------------------------------------------------------------------------
__global__ void rope_split(const float* __restrict__ cosp,
                           const float* __restrict__ sinp)
{
    int i = blockIdx.x * blockDim.x + threadIdx.x;
    if (i >= S_ * HID_ / 2) return;
    int s   = i / (HID_ / 2);
    int c2  = i - s * (HID_ / 2);
    int col = c2 * 2;
    int h   = col / D_;
    int d   = col - h * D_;   // even; d and d+1 on the same side of 40

    const float* base = g_qkv + (size_t)s * THREE_HID;
    float2 qv = *(const float2*)(base + col);
    float2 kv = *(const float2*)(base + HID_ + col);
    float2 vv = *(const float2*)(base + 2 * HID_ + col);
    float2 cc = *(const float2*)(cosp + s * D_ + d);
    float2 sn = *(const float2*)(sinp + s * D_ + d);

    int off = (d < 40) ? (col + 40) : (col - 40);
    float sgn = (d < 40) ? -1.f : 1.f;
    float2 qr = *(const float2*)(base + off);
    float2 kr = *(const float2*)(base + HID_ + off);

    const float inv_scale = rsqrtf((float)D_);
    float qf0 = (qv.x * cc.x + sgn * qr.x * sn.x) * inv_scale;
    float qf1 = (qv.y * cc.y + sgn * qr.y * sn.y) * inv_scale;
    float kf0 = kv.x * cc.x + sgn * kr.x * sn.x;
    float kf1 = kv.y * cc.y + sgn * kr.y * sn.y;

    size_t o = (size_t)h * S_ * D_ + (size_t)s * D_ + d;   // even -> 4B aligned
    uint32_t qh = pk2(qf0, qf1);
    *(uint32_t*)(g_qhi + o) = qh;
    *(uint32_t*)(g_qlo + o) = pk2(qf0 - lo_of(qh), qf1 - hi_of(qh));
    uint32_t kh = pk2(kf0, kf1);
    *(uint32_t*)(g_khi + o) = kh;
    *(uint32_t*)(g_klo + o) = pk2(kf0 - lo_of(kh), kf1 - hi_of(kh));
    uint32_t vh = pk2(vv.x, vv.y);
    *(uint32_t*)(g_vhi + o) = vh;
    *(uint32_t*)(g_vlo + o) = pk2(vv.x - lo_of(vh), vv.y - hi_of(vh));
}

// ---------------------------------------------------------------------------
// HMMA flash attention. 64 q-rows/CTA, 64k tiles, 4 warps, 2 CTAs/SM.
// ---------------------------------------------------------------------------
#define ATT_STRIDE 88
#define Q_BYTES (64 * ATT_STRIDE * 2)     // 11264
#define T_BYTES (64 * ATT_STRIDE * 2)     // 11264
#define OFF_QH 0
#define OFF_QL Q_BYTES
#define OFF_KH (2 * Q_BYTES)
#define OFF_KL (2 * Q_BYTES + 2 * T_BYTES)
#define OFF_VH (2 * Q_BYTES + 4 * T_BYTES)
#define OFF_VL (2 * Q_BYTES + 6 * T_BYTES)
#define ATTN_SMEM_BYTES (2 * Q_BYTES + 8 * T_BYTES)   // 112640

__global__ __launch_bounds__(128, 2) void attn_mma()
{
    extern __shared__ char smc[];
    const uint32_t sb = smem_u32(smc);

    const int bx = blockIdx.x;
    const int qt = bx & 15;           // 16 q-tiles of 64 rows
    const int h  = (bx >> 4) & 15;
    const int c  = bx >> 8;

    const int tid = threadIdx.x;
    const int lane = tid & 31, w = tid >> 5;   // w: 0..3
    const int quad = lane >> 3, l8 = lane & 7;

    const size_t hq = (size_t)h * S_ * D_ + (size_t)(c * L_ + qt * 64) * D_;
    const size_t hk = (size_t)h * S_ * D_ + (size_t)(c * L_) * D_;

    for (int i = tid; i < 640; i += 128) {
        int row = i / 10, seg = i - row * 10;
        uint32_t off = (uint32_t)(row * ATT_STRIDE + seg * 8) * 2;
        size_t g = hq + (size_t)row * 80 + seg * 8;
        CPA16(sb + OFF_QH + off, g_qhi + g);
        CPA16(sb + OFF_QL + off, g_qlo + g);
    }
    for (int i = tid; i < 640; i += 128) {
        int row = i / 10, seg = i - row * 10;
        uint32_t off = (uint32_t)(row * ATT_STRIDE + seg * 8) * 2;
        size_t g = hk + (size_t)row * 80 + seg * 8;
        CPA16(sb + OFF_KH + off, g_khi + g);
        CPA16(sb + OFF_KL + off, g_klo + g);
        CPA16(sb + OFF_VH + off, g_vhi + g);
        CPA16(sb + OFF_VL + off, g_vlo + g);
    }
    asm volatile("cp.async.commit_group;" ::: "memory");

    float m_a = -1e30f, m_b = -1e30f, l_a = 0.f, l_b = 0.f;
    float out[10][4];
#pragma unroll
    for (int vt = 0; vt < 10; vt++)
#pragma unroll
        for (int r = 0; r < 4; r++) out[vt][r] = 0.f;

    for (int t = 0; t < 16; t++) {
        if (t + 1 < 16) {
            const uint32_t s1 = ((t + 1) & 1) * T_BYTES;
            const size_t tb = hk + (size_t)(t + 1) * 64 * 80;
            for (int i = tid; i < 640; i += 128) {
                int row = i / 10, seg = i - row * 10;
                uint32_t off = (uint32_t)(row * ATT_STRIDE + seg * 8) * 2 + s1;
                size_t g = tb + (size_t)row * 80 + seg * 8;
                CPA16(sb + OFF_KH + off, g_khi + g);
                CPA16(sb + OFF_KL + off, g_klo + g);
                CPA16(sb + OFF_VH + off, g_vhi + g);
                CPA16(sb + OFF_VL + off, g_vlo + g);
            }
            asm volatile("cp.async.commit_group;" ::: "memory");
            asm volatile("cp.async.wait_group 1;" ::: "memory");
        } else {
            asm volatile("cp.async.wait_group 0;" ::: "memory");
        }
        __syncthreads();

        const uint32_t stg = (t & 1) * T_BYTES;
        const uint32_t KHs = sb + OFF_KH + stg;
        const uint32_t KLs = sb + OFF_KL + stg;
        const uint32_t VHs = sb + OFF_VH + stg;
        const uint32_t VLs = sb + OFF_VL + stg;

        float sc[8][4];
#pragma unroll
        for (int nt = 0; nt < 8; nt++)
#pragma unroll
            for (int r = 0; r < 4; r++) sc[nt][r] = 0.f;

        const int arow = w * 16 + (quad & 1) * 8 + l8;
#pragma unroll
        for (int kk = 0; kk < 5; kk++) {
            uint32_t ah[4], al[4], bh[4][4], bl[4][4];
            uint32_t aoff = (uint32_t)(arow * ATT_STRIDE + kk * 16 + (quad >> 1) * 8) * 2;
            LDSM4(ah, sb + OFF_QH + aoff);
            LDSM4(al, sb + OFF_QL + aoff);
#pragma unroll
            for (int nj = 0; nj < 4; nj++) {
                uint32_t boff = (uint32_t)((nj * 16 + (quad >> 1) * 8 + l8) * ATT_STRIDE
                                           + kk * 16 + (quad & 1) * 8) * 2;
                LDSM4(bh[nj], KHs + boff);
                LDSM4(bl[nj], KLs + boff);
            }
#pragma unroll
            for (int nj = 0; nj < 4; nj++) {
                MMA4(sc[2 * nj],     ah, bh[nj][0], bh[nj][1]);
                MMA4(sc[2 * nj + 1], ah, bh[nj][2], bh[nj][3]);
            }
#pragma unroll
            for (int nj = 0; nj < 4; nj++) {
                MMA4(sc[2 * nj],     ah, bl[nj][0], bl[nj][1]);
                MMA4(sc[2 * nj + 1], ah, bl[nj][2], bl[nj][3]);
            }
#pragma unroll
            for (int nj = 0; nj < 4; nj++) {
                MMA4(sc[2 * nj],     al, bh[nj][0], bh[nj][1]);
                MMA4(sc[2 * nj + 1], al, bh[nj][2], bh[nj][3]);
            }
        }

        float mxa = sc[0][0], mxb = sc[0][2];
#pragma unroll
        for (int nt = 0; nt < 8; nt++) {
            mxa = fmaxf(mxa, fmaxf(sc[nt][0], sc[nt][1]));
            mxb = fmaxf(mxb, fmaxf(sc[nt][2], sc[nt][3]));
        }
        mxa = fmaxf(mxa, __shfl_xor_sync(0xffffffffu, mxa, 1));
        mxa = fmaxf(mxa, __shfl_xor_sync(0xffffffffu, mxa, 2));
        mxb = fmaxf(mxb, __shfl_xor_sync(0xffffffffu, mxb, 1));
        mxb = fmaxf(mxb, __shfl_xor_sync(0xffffffffu, mxb, 2));
        float nma = fmaxf(m_a, mxa), nmb = fmaxf(m_b, mxb);
        float ca  = __expf(m_a - nma), cb = __expf(m_b - nmb);
        m_a = nma; m_b = nmb;

        float sa = 0.f, sbv = 0.f;
#pragma unroll
        for (int nt = 0; nt < 8; nt++) {
            sc[nt][0] = __expf(sc[nt][0] - m_a);
            sc[nt][1] = __expf(sc[nt][1] - m_a);
            sc[nt][2] = __expf(sc[nt][2] - m_b);
            sc[nt][3] = __expf(sc[nt][3] - m_b);
            sa  += sc[nt][0] + sc[nt][1];
            sbv += sc[nt][2] + sc[nt][3];
        }
        sa  += __shfl_xor_sync(0xffffffffu, sa, 1);
        sa  += __shfl_xor_sync(0xffffffffu, sa, 2);
        sbv += __shfl_xor_sync(0xffffffffu, sbv, 1);
        sbv += __shfl_xor_sync(0xffffffffu, sbv, 2);
        l_a = l_a * ca + sa;
        l_b = l_b * cb + sbv;

        uint32_t Ph[4][4], Pl[4][4];
#pragma unroll
        for (int kk = 0; kk < 4; kk++) {
#pragma unroll
            for (int half = 0; half < 2; half++) {
                int nt = 2 * kk + half;
                uint32_t h0 = pk2(sc[nt][0], sc[nt][1]);
                uint32_t h1 = pk2(sc[nt][2], sc[nt][3]);
                Ph[kk][2 * half + 0] = h0;
                Ph[kk][2 * half + 1] = h1;
                Pl[kk][2 * half + 0] = pk2(sc[nt][0] - lo_of(h0), sc[nt][1] - hi_of(h0));
                Pl[kk][2 * half + 1] = pk2(sc[nt][2] - lo_of(h1), sc[nt][3] - hi_of(h1));
            }
        }

#pragma unroll
        for (int vt = 0; vt < 10; vt++) {
            out[vt][0] *= ca; out[vt][1] *= ca;
            out[vt][2] *= cb; out[vt][3] *= cb;
        }

#pragma unroll
        for (int kk = 0; kk < 4; kk++) {
#pragma unroll
            for (int vj = 0; vj < 5; vj++) {
                uint32_t vhf[4], vlf[4];
                uint32_t voff = (uint32_t)((kk * 16 + (quad & 1) * 8 + l8) * ATT_STRIDE
                                           + vj * 16 + (quad >> 1) * 8) * 2;
                LDSM4T(vhf, VHs + voff);
                LDSM4T(vlf, VLs + voff);
                MMA4(out[2 * vj],     Ph[kk], vhf[0], vhf[1]);
                MMA4(out[2 * vj + 1], Ph[kk], vhf[2], vhf[3]);
                MMA4(out[2 * vj],     Ph[kk], vlf[0], vlf[1]);
                MMA4(out[2 * vj + 1], Ph[kk], vlf[2], vlf[3]);
                MMA4(out[2 * vj],     Pl[kk], vhf[0], vhf[1]);
                MMA4(out[2 * vj + 1], Pl[kk], vhf[2], vhf[3]);
            }
        }
        __syncthreads();
    }

    float ila = 1.f / l_a, ilb = 1.f / l_b;
    int ra = c * L_ + qt * 64 + w * 16 + (lane >> 2);
    int colb = h * D_ + (lane & 3) * 2;
#pragma unroll
    for (int vt = 0; vt < 10; vt++) {
        int col = colb + vt * 8;
        float v0 = out[vt][0] * ila, v1 = out[vt][1] * ila;
        uint32_t hp = pk2(v0, v1);
        uint32_t lp = pk2(v0 - lo_of(hp), v1 - hi_of(hp));
        *(uint32_t*)(g_ahi + (size_t)ra * HID_ + col) = hp;
        *(uint32_t*)(g_alo + (size_t)ra * HID_ + col) = lp;
        float v2 = out[vt][2] * ilb, v3 = out[vt][3] * ilb;
        hp = pk2(v2, v3);
        lp = pk2(v2 - lo_of(hp), v3 - hi_of(hp));
        *(uint32_t*)(g_ahi + (size_t)(ra + 8) * HID_ + col) = hp;
        *(uint32_t*)(g_alo + (size_t)(ra + 8) * HID_ + col) = lp;
    }
}

// ---------------------------------------------------------------------------
// Launch pipeline (weight conversions forked onto side streams)
// ---------------------------------------------------------------------------
extern "C" void kernel_launch(void* const* d_in, const int* in_sizes, int n_in,
                              void* d_out, int out_size)
{
    const float* x     = (const float*)d_in[0];
    const float* cosp  = (const float*)d_in[1];
    const float* sinp  = (const float*)d_in[2];
    const float* Wqkv  = (const float*)d_in[3];
    const float* bqkv  = (const float*)d_in[4];
    const float* Wproj = (const float*)d_in[5];
    const float* bproj = (const float*)d_in[6];
    float* out = (float*)d_out;

    float* qkv_p;
    __nv_bfloat16 *xhi, *xlo, *wqh, *wql, *wph, *wpl, *ahi, *alo;
    cudaGetSymbolAddress((void**)&qkv_p, g_qkv);
    cudaGetSymbolAddress((void**)&xhi, g_xhi);
    cudaGetSymbolAddress((void**)&xlo, g_xlo);
    cudaGetSymbolAddress((void**)&wqh, g_wqt_hi);
    cudaGetSymbolAddress((void**)&wql, g_wqt_lo);
    cudaGetSymbolAddress((void**)&wph, g_wpt_hi);
    cudaGetSymbolAddress((void**)&wpl, g_wpt_lo);
    cudaGetSymbolAddress((void**)&ahi, g_ahi);
    cudaGetSymbolAddress((void**)&alo, g_alo);

    static int init_done = 0;
    static cudaStream_t s1, s2;
    static cudaEvent_t evA, ev1, ev2;
    if (!init_done) {
        cudaFuncSetAttribute(attn_mma,
                             cudaFuncAttributeMaxDynamicSharedMemorySize,
                             ATTN_SMEM_BYTES);
        cudaFuncSetAttribute(mma_gemm_bias_sm,
                             cudaFuncAttributeMaxDynamicSharedMemorySize,
                             GEMM_SM_SMEM_BYTES);
        cudaStreamCreateWithFlags(&s1, cudaStreamNonBlocking);
        cudaStreamCreateWithFlags(&s2, cudaStreamNonBlocking);
        cudaEventCreateWithFlags(&evA, cudaEventDisableTiming);
        cudaEventCreateWithFlags(&ev1, cudaEventDisableTiming);
        cudaEventCreateWithFlags(&ev2, cudaEventDisableTiming);
        init_done = 1;
    }

    // fork: weight conversions on side streams
    cudaEventRecord(evA, 0);
    cudaStreamWaitEvent(s1, evA, 0);
    cudaStreamWaitEvent(s2, evA, 0);
    split_t<<<dim3(THREE_HID / 32, HID_ / 32), dim3(32, 8), 0, s1>>>(
        Wqkv, wqh, wql, HID_, THREE_HID);
    cudaEventRecord(ev1, s1);
    split_t<<<dim3(HID_ / 32, HID_ / 32), dim3(32, 8), 0, s2>>>(
        Wproj, wph, wpl, HID_, HID_);
    cudaEventRecord(ev2, s2);

    // main stream: x conversion
    split_rows<<<(S_ * HID_ / 4 + 255) / 256, 256>>>(x, xhi, xlo, S_ * HID_ / 4);

    // join Wqkv before QKV GEMM
    cudaStreamWaitEvent(0, ev1, 0);
    mma_gemm_bias_sm<<<dim3(THREE_HID / 128, S_ / 64), 128, GEMM_SM_SMEM_BYTES>>>(
        xhi, xlo, wqh, wql, bqkv, qkv_p, S_, THREE_HID, HID_);

    rope_split<<<(S_ * HID_ / 2 + 255) / 256, 256>>>(cosp, sinp);

    attn_mma<<<C_ * H_ * (L_ / 64), 128, ATTN_SMEM_BYTES>>>();

    // join Wproj before proj GEMM (hidden under QKV+attn)
    cudaStreamWaitEvent(0, ev2, 0);
    mma_gemm_bias_sm<<<dim3(HID_ / 128, S_ / 64), 128, GEMM_SM_SMEM_BYTES>>>(
        ahi, alo, wph, wpl, bproj, out, S_, HID_, HID_);
}

// round 13
// speedup vs baseline: 1.0659x; 1.0403x over previous
#include <cuda_runtime.h>
#include <cuda_bf16.h>
#include <cstdint>
#include <math.h>

#define S_        8192
#define HID_      1280
#define H_        16
#define D_        80
#define C_        8
#define L_        1024
#define THREE_HID 3840

// ---------------------------------------------------------------------------
// Scratch (allocation-free rule: __device__ globals)
// ---------------------------------------------------------------------------
__device__ float g_qkv[(size_t)S_ * THREE_HID];
__device__ __nv_bfloat16 g_xhi[(size_t)S_ * HID_];
__device__ __nv_bfloat16 g_xlo[(size_t)S_ * HID_];
__device__ __nv_bfloat16 g_wqt_hi[(size_t)THREE_HID * HID_];  // Wqkv^T [N][K]
__device__ __nv_bfloat16 g_wqt_lo[(size_t)THREE_HID * HID_];
__device__ __nv_bfloat16 g_wpt_hi[(size_t)HID_ * HID_];       // Wproj^T [N][K]
__device__ __nv_bfloat16 g_wpt_lo[(size_t)HID_ * HID_];
__device__ __nv_bfloat16 g_ahi[(size_t)S_ * HID_];            // attn out hi/lo
__device__ __nv_bfloat16 g_alo[(size_t)S_ * HID_];
__device__ __nv_bfloat16 g_qhi[(size_t)H_ * S_ * D_];
__device__ __nv_bfloat16 g_qlo[(size_t)H_ * S_ * D_];
__device__ __nv_bfloat16 g_khi[(size_t)H_ * S_ * D_];
__device__ __nv_bfloat16 g_klo[(size_t)H_ * S_ * D_];
__device__ __nv_bfloat16 g_vhi[(size_t)H_ * S_ * D_];
__device__ __nv_bfloat16 g_vlo[(size_t)H_ * S_ * D_];

__device__ __forceinline__ uint32_t smem_u32(const void* p) {
    uint32_t a;
    asm("{ .reg .u64 t; cvta.to.shared.u64 t, %1; cvt.u32.u64 %0, t; }"
        : "=r"(a) : "l"(p));
    return a;
}
__device__ __forceinline__ uint32_t pk2(float lo, float hi) {
    uint32_t r;
    asm("cvt.rn.bf16x2.f32 %0, %1, %2;" : "=r"(r) : "f"(hi), "f"(lo));
    return r;
}
__device__ __forceinline__ float lo_of(uint32_t p) { return __uint_as_float(p << 16); }
__device__ __forceinline__ float hi_of(uint32_t p) { return __uint_as_float(p & 0xffff0000u); }

#define MMA4(cc, aa, b0, b1)                                                    \
    asm volatile("mma.sync.aligned.m16n8k16.row.col.f32.bf16.bf16.f32 "         \
                 "{%0,%1,%2,%3},{%4,%5,%6,%7},{%8,%9},{%0,%1,%2,%3};"           \
                 : "+f"((cc)[0]), "+f"((cc)[1]), "+f"((cc)[2]), "+f"((cc)[3])   \
                 : "r"((aa)[0]), "r"((aa)[1]), "r"((aa)[2]), "r"((aa)[3]),      \
                   "r"(b0), "r"(b1))
#define LDSM4(r, addr)                                                          \
    asm volatile("ldmatrix.sync.aligned.m8n8.x4.shared.b16 {%0,%1,%2,%3}, [%4];"\
                 : "=r"((r)[0]), "=r"((r)[1]), "=r"((r)[2]), "=r"((r)[3])       \
                 : "r"(addr))
#define LDSM4T(r, addr)                                                         \
    asm volatile("ldmatrix.sync.aligned.m8n8.x4.trans.shared.b16 {%0,%1,%2,%3}, [%4];" \
                 : "=r"((r)[0]), "=r"((r)[1]), "=r"((r)[2]), "=r"((r)[3])       \
                 : "r"(addr))
#define CPA16(dst, src)                                                         \
    asm volatile("cp.async.cg.shared.global [%0], [%1], 16;" :: "r"(dst), "l"(src))

// ---------------------------------------------------------------------------
// bf16-split conversion kernels (vectorized)
// ---------------------------------------------------------------------------
__global__ void split_rows(const float* __restrict__ in,
                           __nv_bfloat16* __restrict__ hi,
                           __nv_bfloat16* __restrict__ lo, int n4)
{
    int i = blockIdx.x * blockDim.x + threadIdx.x;
    if (i >= n4) return;
    float4 v = *(const float4*)(in + 4 * (size_t)i);
    uint32_t h01 = pk2(v.x, v.y);
    uint32_t h23 = pk2(v.z, v.w);
    uint32_t l01 = pk2(v.x - lo_of(h01), v.y - hi_of(h01));
    uint32_t l23 = pk2(v.z - lo_of(h23), v.w - hi_of(h23));
    uint2 hv; hv.x = h01; hv.y = h23;
    uint2 lv; lv.x = l01; lv.y = l23;
    *(uint2*)(hi + 4 * (size_t)i) = hv;
    *(uint2*)(lo + 4 * (size_t)i) = lv;
}

__global__ void split_t(const float* __restrict__ W,
                        __nv_bfloat16* __restrict__ hi,
                        __nv_bfloat16* __restrict__ lo, int K, int N)
{
    __shared__ float t[32][33];
    int n0 = blockIdx.x * 32, k0 = blockIdx.y * 32;
    int tx = threadIdx.x, ty = threadIdx.y;   // (32, 8)
#pragma unroll
    for (int i = 0; i < 32; i += 8)
        t[ty + i][tx] = W[(size_t)(k0 + ty + i) * N + n0 + tx];
    __syncthreads();
#pragma unroll
    for (int i = 0; i < 32; i += 8) {
        float v = t[tx][ty + i];
        __nv_bfloat16 h = __float2bfloat16(v);
        size_t o = (size_t)(n0 + ty + i) * K + k0 + tx;
        hi[o] = h;
        lo[o] = __float2bfloat16(v - __bfloat162float(h));
    }
}

// ---------------------------------------------------------------------------
// Small-CTA bf16-split GEMM: C = A @ B^T + bias.
// 64(M) x 128(N) tile, BK=32, 128 threads (4 warps, warp tile 32x64),
// double-buffered cp.async, 3 CTAs/SM.  3-term split.
// (Callers pass pre-offset A / C pointers for row-half pipelining.)
// ---------------------------------------------------------------------------
#define AST 40
#define A64_BYTES (64 * AST * 2)           // 5120
#define B128_BYTES (128 * AST * 2)         // 10240
#define STAGE_SM (2 * A64_BYTES + 2 * B128_BYTES)   // 30720
#define GEMM_SM_SMEM_BYTES (2 * STAGE_SM)           // 61440

__global__ __launch_bounds__(128, 3) void mma_gemm_bias_sm(
    const __nv_bfloat16* __restrict__ Ahi, const __nv_bfloat16* __restrict__ Alo,
    const __nv_bfloat16* __restrict__ Bhi, const __nv_bfloat16* __restrict__ Blo,
    const float* __restrict__ bias, float* __restrict__ Cm,
    int M, int N, int K)
{
    extern __shared__ __nv_bfloat16 smb[];
    const uint32_t sb = smem_u32(smb);

    const int tid  = threadIdx.x;
    const int lane = tid & 31, warp = tid >> 5;   // 0..3
    const int warpM = warp & 1;
    const int warpN = warp >> 1;
    const int quad = lane >> 3, l8 = lane & 7;
    const int tileN = blockIdx.x, tileM = blockIdx.y;

    const __nv_bfloat16* gAh = Ahi + (size_t)(tileM * 64) * K;
    const __nv_bfloat16* gAl = Alo + (size_t)(tileM * 64) * K;
    const __nv_bfloat16* gBh = Bhi + (size_t)(tileN * 128) * K;
    const __nv_bfloat16* gBl = Blo + (size_t)(tileN * 128) * K;

    float c[2][8][4];
#pragma unroll
    for (int mi = 0; mi < 2; mi++)
#pragma unroll
        for (int nt = 0; nt < 8; nt++)
#pragma unroll
            for (int r = 0; r < 4; r++) c[mi][nt][r] = 0.f;

    const int nch = K >> 5;

    auto issue = [&](int ch, int buf) {
        const int k0 = ch * 32;
        const uint32_t base = sb + (uint32_t)(buf * STAGE_SM);
#pragma unroll
        for (int p = 0; p < 2; p++) {    // A: 64 rows x 4 segs
            int idx = tid + p * 128;
            int row = idx >> 2, seg = idx & 3;
            uint32_t so = (uint32_t)((row * AST + seg * 8) * 2);
            size_t go = (size_t)row * K + k0 + seg * 8;
            CPA16(base + so,             gAh + go);
            CPA16(base + A64_BYTES + so, gAl + go);
        }
#pragma unroll
        for (int p = 0; p < 4; p++) {    // B: 128 rows x 4 segs
            int idx = tid + p * 128;
            int row = idx >> 2, seg = idx & 3;
            uint32_t so = (uint32_t)((row * AST + seg * 8) * 2);
            size_t go = (size_t)row * K + k0 + seg * 8;
            CPA16(base + 2 * A64_BYTES + so,              gBh + go);
            CPA16(base + 2 * A64_BYTES + B128_BYTES + so, gBl + go);
        }
        asm volatile("cp.async.commit_group;" ::: "memory");
    };

    issue(0, 0);

    for (int ch = 0; ch < nch; ch++) {
        if (ch + 1 < nch) {
            issue(ch + 1, (ch + 1) & 1);
            asm volatile("cp.async.wait_group 1;" ::: "memory");
        } else {
            asm volatile("cp.async.wait_group 0;" ::: "memory");
        }
        __syncthreads();

        const uint32_t base = sb + (uint32_t)((ch & 1) * STAGE_SM);
        const uint32_t aHb = base;
        const uint32_t aLb = base + A64_BYTES;
        const uint32_t bHb = base + 2 * A64_BYTES;
        const uint32_t bLb = base + 2 * A64_BYTES + B128_BYTES;

#pragma unroll
        for (int s = 0; s < 2; s++) {
            uint32_t ah[2][4], al[2][4], bh[4][4], bl[4][4];
#pragma unroll
            for (int mi = 0; mi < 2; mi++) {
                int row = warpM * 32 + mi * 16 + (quad & 1) * 8 + l8;
                int ke  = s * 16 + (quad >> 1) * 8;
                LDSM4(ah[mi], aHb + (uint32_t)((row * AST + ke) * 2));
                LDSM4(al[mi], aLb + (uint32_t)((row * AST + ke) * 2));
            }
#pragma unroll
            for (int nj = 0; nj < 4; nj++) {
                int nrow = warpN * 64 + nj * 16 + (quad >> 1) * 8 + l8;
                int ke   = s * 16 + (quad & 1) * 8;
                LDSM4(bh[nj], bHb + (uint32_t)((nrow * AST + ke) * 2));
                LDSM4(bl[nj], bLb + (uint32_t)((nrow * AST + ke) * 2));
            }
#pragma unroll
            for (int mi = 0; mi < 2; mi++)
#pragma unroll
                for (int nt = 0; nt < 8; nt++) {
                    int nj = nt >> 1, hh = (nt & 1) * 2;
                    MMA4(c[mi][nt], ah[mi], bh[nj][hh], bh[nj][hh + 1]);
                }
#pragma unroll
            for (int mi = 0; mi < 2; mi++)
#pragma unroll
                for (int nt = 0; nt < 8; nt++) {
                    int nj = nt >> 1, hh = (nt & 1) * 2;
                    MMA4(c[mi][nt], ah[mi], bl[nj][hh], bl[nj][hh + 1]);
                }
#pragma unroll
            for (int mi = 0; mi < 2; mi++)
#pragma unroll
                for (int nt = 0; nt < 8; nt++) {
                    int nj = nt >> 1, hh = (nt & 1) * 2;
                    MMA4(c[mi][nt], al[mi], bh[nj][hh], bh[nj][hh + 1]);
                }
        }
        __syncthreads();
    }

    const int m0 = tileM * 64 + warpM * 32;
    const int n0 = tileN * 128 + warpN * 64;
    const int rq = lane >> 2, cq = (lane & 3) * 2;
#pragma unroll
    for (int mi = 0; mi < 2; mi++) {
#pragma unroll
        for (int nt = 0; nt < 8; nt++) {
            int col = n0 + nt * 8 + cq;
            float2 b2 = *(const float2*)(bias + col);
            int r0 = m0 + mi * 16 + rq;
            float2 o0, o1;
            o0.x = c[mi][nt][0] + b2.x; o0.y = c[mi][nt][1] + b2.y;
            o1.x = c[mi][nt][2] + b2.x; o1.y = c[mi][nt][3] + b2.y;
            *(float2*)(Cm + (size_t)r0 * N + col)       = o0;
            *(float2*)(Cm + (size_t)(r0 + 8) * N + col) = o1;
        }
    }
}

// ---------------------------------------------------------------------------
// RoPE + split (vectorized, 2 elems/thread), row-half via s0 offset.
// ---------------------------------------------------------------------------
__global__ void rope_split(const float* __restrict__ cosp,
                           const float* __restrict__ sinp, int s0, int nhalf)
{
    int i = blockIdx.x * blockDim.x + threadIdx.x;
    if (i >= nhalf) return;
    int s   = s0 + i / (HID_ / 2);
    int c2  = i - (s - s0) * (HID_ / 2);
    int col = c2 * 2;
    int h   = col / D_;
    int d   = col - h * D_;   // even; d and d+1 on the same side of 40

    const float* base = g_qkv + (size_t)s * THREE_HID;
    float2 qv = *(const float2*)(base + col);
    float2 kv = *(const float2*)(base + HID_ + col);
    float2 vv = *(const float2*)(base + 2 * HID_ + col);
    float2 cc = *(const float2*)(cosp + s * D_ + d);
    float2 sn = *(const float2*)(sinp + s * D_ + d);

    int off = (d < 40) ? (col + 40) : (col - 40);
    float sgn = (d < 40) ? -1.f : 1.f;
    float2 qr = *(const float2*)(base + off);
    float2 kr = *(const float2*)(base + HID_ + off);

    const float inv_scale = rsqrtf((float)D_);
    float qf0 = (qv.x * cc.x + sgn * qr.x * sn.x) * inv_scale;
    float qf1 = (qv.y * cc.y + sgn * qr.y * sn.y) * inv_scale;
    float kf0 = kv.x * cc.x + sgn * kr.x * sn.x;
    float kf1 = kv.y * cc.y + sgn * kr.y * sn.y;

    size_t o = (size_t)h * S_ * D_ + (size_t)s * D_ + d;
    uint32_t qh = pk2(qf0, qf1);
    *(uint32_t*)(g_qhi + o) = qh;
    *(uint32_t*)(g_qlo + o) = pk2(qf0 - lo_of(qh), qf1 - hi_of(qh));
    uint32_t kh = pk2(kf0, kf1);
    *(uint32_t*)(g_khi + o) = kh;
    *(uint32_t*)(g_klo + o) = pk2(kf0 - lo_of(kh), kf1 - hi_of(kh));
    uint32_t vh = pk2(vv.x, vv.y);
    *(uint32_t*)(g_vhi + o) = vh;
    *(uint32_t*)(g_vlo + o) = pk2(vv.x - lo_of(vh), vv.y - hi_of(vh));
}

// ---------------------------------------------------------------------------
// HMMA flash attention. 64 q-rows/CTA, 64k tiles, 4 warps, 2 CTAs/SM.
// Chunk-half via c0 offset.
// ---------------------------------------------------------------------------
#define ATT_STRIDE 88
#define Q_BYTES (64 * ATT_STRIDE * 2)     // 11264
#define T_BYTES (64 * ATT_STRIDE * 2)     // 11264
#define OFF_QH 0
#define OFF_QL Q_BYTES
#define OFF_KH (2 * Q_BYTES)
#define OFF_KL (2 * Q_BYTES + 2 * T_BYTES)
#define OFF_VH (2 * Q_BYTES + 4 * T_BYTES)
#define OFF_VL (2 * Q_BYTES + 6 * T_BYTES)
#define ATTN_SMEM_BYTES (2 * Q_BYTES + 8 * T_BYTES)   // 112640

__global__ __launch_bounds__(128, 2) void attn_mma(int c0)
{
    extern __shared__ char smc[];
    const uint32_t sb = smem_u32(smc);

    const int bx = blockIdx.x;
    const int qt = bx & 15;           // 16 q-tiles of 64 rows
    const int h  = (bx >> 4) & 15;
    const int c  = c0 + (bx >> 8);

    const int tid = threadIdx.x;
    const int lane = tid & 31, w = tid >> 5;   // w: 0..3
    const int quad = lane >> 3, l8 = lane & 7;

    const size_t hq = (size_t)h * S_ * D_ + (size_t)(c * L_ + qt * 64) * D_;
    const size_t hk = (size_t)h * S_ * D_ + (size_t)(c * L_) * D_;

    for (int i = tid; i < 640; i += 128) {
        int row = i / 10, seg = i - row * 10;
        uint32_t off = (uint32_t)(row * ATT_STRIDE + seg * 8) * 2;
        size_t g = hq + (size_t)row * 80 + seg * 8;
        CPA16(sb + OFF_QH + off, g_qhi + g);
        CPA16(sb + OFF_QL + off, g_qlo + g);
    }
    for (int i = tid; i < 640; i += 128) {
        int row = i / 10, seg = i - row * 10;
        uint32_t off = (uint32_t)(row * ATT_STRIDE + seg * 8) * 2;
        size_t g = hk + (size_t)row * 80 + seg * 8;
        CPA16(sb + OFF_KH + off, g_khi + g);
        CPA16(sb + OFF_KL + off, g_klo + g);
        CPA16(sb + OFF_VH + off, g_vhi + g);
        CPA16(sb + OFF_VL + off, g_vlo + g);
    }
    asm volatile("cp.async.commit_group;" ::: "memory");

    float m_a = -1e30f, m_b = -1e30f, l_a = 0.f, l_b = 0.f;
    float out[10][4];
#pragma unroll
    for (int vt = 0; vt < 10; vt++)
#pragma unroll
        for (int r = 0; r < 4; r++) out[vt][r] = 0.f;

    for (int t = 0; t < 16; t++) {
        if (t + 1 < 16) {
            const uint32_t s1 = ((t + 1) & 1) * T_BYTES;
            const size_t tb = hk + (size_t)(t + 1) * 64 * 80;
            for (int i = tid; i < 640; i += 128) {
                int row = i / 10, seg = i - row * 10;
                uint32_t off = (uint32_t)(row * ATT_STRIDE + seg * 8) * 2 + s1;
                size_t g = tb + (size_t)row * 80 + seg * 8;
                CPA16(sb + OFF_KH + off, g_khi + g);
                CPA16(sb + OFF_KL + off, g_klo + g);
                CPA16(sb + OFF_VH + off, g_vhi + g);
                CPA16(sb + OFF_VL + off, g_vlo + g);
            }
            asm volatile("cp.async.commit_group;" ::: "memory");
            asm volatile("cp.async.wait_group 1;" ::: "memory");
        } else {
            asm volatile("cp.async.wait_group 0;" ::: "memory");
        }
        __syncthreads();

        const uint32_t stg = (t & 1) * T_BYTES;
        const uint32_t KHs = sb + OFF_KH + stg;
        const uint32_t KLs = sb + OFF_KL + stg;
        const uint32_t VHs = sb + OFF_VH + stg;
        const uint32_t VLs = sb + OFF_VL + stg;

        float sc[8][4];
#pragma unroll
        for (int nt = 0; nt < 8; nt++)
#pragma unroll
            for (int r = 0; r < 4; r++) sc[nt][r] = 0.f;

        const int arow = w * 16 + (quad & 1) * 8 + l8;
#pragma unroll
        for (int kk = 0; kk < 5; kk++) {
            uint32_t ah[4], al[4], bh[4][4], bl[4][4];
            uint32_t aoff = (uint32_t)(arow * ATT_STRIDE + kk * 16 + (quad >> 1) * 8) * 2;
            LDSM4(ah, sb + OFF_QH + aoff);
            LDSM4(al, sb + OFF_QL + aoff);
#pragma unroll
            for (int nj = 0; nj < 4; nj++) {
                uint32_t boff = (uint32_t)((nj * 16 + (quad >> 1) * 8 + l8) * ATT_STRIDE
                                           + kk * 16 + (quad & 1) * 8) * 2;
                LDSM4(bh[nj], KHs + boff);
                LDSM4(bl[nj], KLs + boff);
            }
#pragma unroll
            for (int nj = 0; nj < 4; nj++) {
                MMA4(sc[2 * nj],     ah, bh[nj][0], bh[nj][1]);
                MMA4(sc[2 * nj + 1], ah, bh[nj][2], bh[nj][3]);
            }
#pragma unroll
            for (int nj = 0; nj < 4; nj++) {
                MMA4(sc[2 * nj],     ah, bl[nj][0], bl[nj][1]);
                MMA4(sc[2 * nj + 1], ah, bl[nj][2], bl[nj][3]);
            }
#pragma unroll
            for (int nj = 0; nj < 4; nj++) {
                MMA4(sc[2 * nj],     al, bh[nj][0], bh[nj][1]);
                MMA4(sc[2 * nj + 1], al, bh[nj][2], bh[nj][3]);
            }
        }

        float mxa = sc[0][0], mxb = sc[0][2];
#pragma unroll
        for (int nt = 0; nt < 8; nt++) {
            mxa = fmaxf(mxa, fmaxf(sc[nt][0], sc[nt][1]));
            mxb = fmaxf(mxb, fmaxf(sc[nt][2], sc[nt][3]));
        }
        mxa = fmaxf(mxa, __shfl_xor_sync(0xffffffffu, mxa, 1));
        mxa = fmaxf(mxa, __shfl_xor_sync(0xffffffffu, mxa, 2));
        mxb = fmaxf(mxb, __shfl_xor_sync(0xffffffffu, mxb, 1));
        mxb = fmaxf(mxb, __shfl_xor_sync(0xffffffffu, mxb, 2));
        float nma = fmaxf(m_a, mxa), nmb = fmaxf(m_b, mxb);
        float ca  = __expf(m_a - nma), cb = __expf(m_b - nmb);
        m_a = nma; m_b = nmb;

        float sa = 0.f, sbv = 0.f;
#pragma unroll
        for (int nt = 0; nt < 8; nt++) {
            sc[nt][0] = __expf(sc[nt][0] - m_a);
            sc[nt][1] = __expf(sc[nt][1] - m_a);
            sc[nt][2] = __expf(sc[nt][2] - m_b);
            sc[nt][3] = __expf(sc[nt][3] - m_b);
            sa  += sc[nt][0] + sc[nt][1];
            sbv += sc[nt][2] + sc[nt][3];
        }
        sa  += __shfl_xor_sync(0xffffffffu, sa, 1);
        sa  += __shfl_xor_sync(0xffffffffu, sa, 2);
        sbv += __shfl_xor_sync(0xffffffffu, sbv, 1);
        sbv += __shfl_xor_sync(0xffffffffu, sbv, 2);
        l_a = l_a * ca + sa;
        l_b = l_b * cb + sbv;

        uint32_t Ph[4][4], Pl[4][4];
#pragma unroll
        for (int kk = 0; kk < 4; kk++) {
#pragma unroll
            for (int half = 0; half < 2; half++) {
                int nt = 2 * kk + half;
                uint32_t h0 = pk2(sc[nt][0], sc[nt][1]);
                uint32_t h1 = pk2(sc[nt][2], sc[nt][3]);
                Ph[kk][2 * half + 0] = h0;
                Ph[kk][2 * half + 1] = h1;
                Pl[kk][2 * half + 0] = pk2(sc[nt][0] - lo_of(h0), sc[nt][1] - hi_of(h0));
                Pl[kk][2 * half + 1] = pk2(sc[nt][2] - lo_of(h1), sc[nt][3] - hi_of(h1));
            }
        }

#pragma unroll
        for (int vt = 0; vt < 10; vt++) {
            out[vt][0] *= ca; out[vt][1] *= ca;
            out[vt][2] *= cb; out[vt][3] *= cb;
        }

#pragma unroll
        for (int kk = 0; kk < 4; kk++) {
#pragma unroll
            for (int vj = 0; vj < 5; vj++) {
                uint32_t vhf[4], vlf[4];
                uint32_t voff = (uint32_t)((kk * 16 + (quad & 1) * 8 + l8) * ATT_STRIDE
                                           + vj * 16 + (quad >> 1) * 8) * 2;
                LDSM4T(vhf, VHs + voff);
                LDSM4T(vlf, VLs + voff);
                MMA4(out[2 * vj],     Ph[kk], vhf[0], vhf[1]);
                MMA4(out[2 * vj + 1], Ph[kk], vhf[2], vhf[3]);
                MMA4(out[2 * vj],     Ph[kk], vlf[0], vlf[1]);
                MMA4(out[2 * vj + 1], Ph[kk], vlf[2], vlf[3]);
                MMA4(out[2 * vj],     Pl[kk], vhf[0], vhf[1]);
                MMA4(out[2 * vj + 1], Pl[kk], vhf[2], vhf[3]);
            }
        }
        __syncthreads();
    }

    float ila = 1.f / l_a, ilb = 1.f / l_b;
    int ra = c * L_ + qt * 64 + w * 16 + (lane >> 2);
    int colb = h * D_ + (lane & 3) * 2;
#pragma unroll
    for (int vt = 0; vt < 10; vt++) {
        int col = colb + vt * 8;
        float v0 = out[vt][0] * ila, v1 = out[vt][1] * ila;
        uint32_t hp = pk2(v0, v1);
        uint32_t lp = pk2(v0 - lo_of(hp), v1 - hi_of(hp));
        *(uint32_t*)(g_ahi + (size_t)ra * HID_ + col) = hp;
        *(uint32_t*)(g_alo + (size_t)ra * HID_ + col) = lp;
        float v2 = out[vt][2] * ilb, v3 = out[vt][3] * ilb;
        hp = pk2(v2, v3);
        lp = pk2(v2 - lo_of(hp), v3 - hi_of(hp));
        *(uint32_t*)(g_ahi + (size_t)(ra + 8) * HID_ + col) = hp;
        *(uint32_t*)(g_alo + (size_t)(ra + 8) * HID_ + col) = lp;
    }
}

// ---------------------------------------------------------------------------
// Launch pipeline: two chunk-half chains on two streams.
// ---------------------------------------------------------------------------
#define HS (S_ / 2)   // 4096 rows per half

extern "C" void kernel_launch(void* const* d_in, const int* in_sizes, int n_in,
                              void* d_out, int out_size)
{
    const float* x     = (const float*)d_in[0];
    const float* cosp  = (const float*)d_in[1];
    const float* sinp  = (const float*)d_in[2];
    const float* Wqkv  = (const float*)d_in[3];
    const float* bqkv  = (const float*)d_in[4];
    const float* Wproj = (const float*)d_in[5];
    const float* bproj = (const float*)d_in[6];
    float* out = (float*)d_out;

    float* qkv_p;
    __nv_bfloat16 *xhi, *xlo, *wqh, *wql, *wph, *wpl, *ahi, *alo;
    cudaGetSymbolAddress((void**)&qkv_p, g_qkv);
    cudaGetSymbolAddress((void**)&xhi, g_xhi);
    cudaGetSymbolAddress((void**)&xlo, g_xlo);
    cudaGetSymbolAddress((void**)&wqh, g_wqt_hi);
    cudaGetSymbolAddress((void**)&wql, g_wqt_lo);
    cudaGetSymbolAddress((void**)&wph, g_wpt_hi);
    cudaGetSymbolAddress((void**)&wpl, g_wpt_lo);
    cudaGetSymbolAddress((void**)&ahi, g_ahi);
    cudaGetSymbolAddress((void**)&alo, g_alo);

    static int init_done = 0;
    static cudaStream_t s1, s2;
    static cudaEvent_t evA, evX, evW1, evW2, evF1, evF2;
    if (!init_done) {
        cudaFuncSetAttribute(attn_mma,
                             cudaFuncAttributeMaxDynamicSharedMemorySize,
                             ATTN_SMEM_BYTES);
        cudaFuncSetAttribute(mma_gemm_bias_sm,
                             cudaFuncAttributeMaxDynamicSharedMemorySize,
                             GEMM_SM_SMEM_BYTES);
        cudaStreamCreateWithFlags(&s1, cudaStreamNonBlocking);
        cudaStreamCreateWithFlags(&s2, cudaStreamNonBlocking);
        cudaEventCreateWithFlags(&evA, cudaEventDisableTiming);
        cudaEventCreateWithFlags(&evX, cudaEventDisableTiming);
        cudaEventCreateWithFlags(&evW1, cudaEventDisableTiming);
        cudaEventCreateWithFlags(&evW2, cudaEventDisableTiming);
        cudaEventCreateWithFlags(&evF1, cudaEventDisableTiming);
        cudaEventCreateWithFlags(&evF2, cudaEventDisableTiming);
        init_done = 1;
    }

    // ---- fork from main ----
    cudaEventRecord(evA, 0);
    cudaStreamWaitEvent(s1, evA, 0);
    cudaStreamWaitEvent(s2, evA, 0);

    // s1: Wqkv conversion; s2: Wproj conversion
    split_t<<<dim3(THREE_HID / 32, HID_ / 32), dim3(32, 8), 0, s1>>>(
        Wqkv, wqh, wql, HID_, THREE_HID);
    cudaEventRecord(evW1, s1);
    split_t<<<dim3(HID_ / 32, HID_ / 32), dim3(32, 8), 0, s2>>>(
        Wproj, wph, wpl, HID_, HID_);
    cudaEventRecord(evW2, s2);

    // main: x conversion (needed by both QKV halves)
    split_rows<<<(S_ * HID_ / 4 + 255) / 256, 256>>>(x, xhi, xlo, S_ * HID_ / 4);
    cudaEventRecord(evX, 0);

    // ---- chain A (s1): half 0 = rows 0..HS-1, chunks 0..3 ----
    cudaStreamWaitEvent(s1, evX, 0);
    mma_gemm_bias_sm<<<dim3(THREE_HID / 128, HS / 64), 128, GEMM_SM_SMEM_BYTES, s1>>>(
        xhi, xlo, wqh, wql, bqkv, qkv_p, HS, THREE_HID, HID_);
    rope_split<<<(HS * HID_ / 2 + 255) / 256, 256, 0, s1>>>(cosp, sinp, 0, HS * HID_ / 2);
    attn_mma<<<(C_ / 2) * H_ * (L_ / 64), 128, ATTN_SMEM_BYTES, s1>>>(0);
    cudaStreamWaitEvent(s1, evW2, 0);
    mma_gemm_bias_sm<<<dim3(HID_ / 128, HS / 64), 128, GEMM_SM_SMEM_BYTES, s1>>>(
        ahi, alo, wph, wpl, bproj, out, HS, HID_, HID_);
    cudaEventRecord(evF1, s1);

    // ---- chain B (s2): half 1 = rows HS..S-1, chunks 4..7 ----
    cudaStreamWaitEvent(s2, evX, 0);
    cudaStreamWaitEvent(s2, evW1, 0);
    mma_gemm_bias_sm<<<dim3(THREE_HID / 128, HS / 64), 128, GEMM_SM_SMEM_BYTES, s2>>>(
        xhi + (size_t)HS * HID_, xlo + (size_t)HS * HID_, wqh, wql, bqkv,
        qkv_p + (size_t)HS * THREE_HID, HS, THREE_HID, HID_);
    rope_split<<<(HS * HID_ / 2 + 255) / 256, 256, 0, s2>>>(cosp, sinp, HS, HS * HID_ / 2);
    attn_mma<<<(C_ / 2) * H_ * (L_ / 64), 128, ATTN_SMEM_BYTES, s2>>>(C_ / 2);
    mma_gemm_bias_sm<<<dim3(HID_ / 128, HS / 64), 128, GEMM_SM_SMEM_BYTES, s2>>>(
        ahi + (size_t)HS * HID_, alo + (size_t)HS * HID_, wph, wpl, bproj,
        out + (size_t)HS * HID_, HS, HID_, HID_);
    cudaEventRecord(evF2, s2);

    // ---- join to main ----
    cudaStreamWaitEvent(0, evF1, 0);
    cudaStreamWaitEvent(0, evF2, 0);
}

// round 16
// speedup vs baseline: 1.0695x; 1.0034x over previous
#include <cuda_runtime.h>
#include <cuda_bf16.h>
#include <cstdint>
#include <math.h>

#define S_        8192
#define HID_      1280
#define H_        16
#define D_        80
#define C_        8
#define L_        1024
#define THREE_HID 3840

// ---------------------------------------------------------------------------
// Scratch (allocation-free rule: __device__ globals)
// ---------------------------------------------------------------------------
__device__ float g_qkv[(size_t)S_ * THREE_HID];
__device__ __nv_bfloat16 g_xhi[(size_t)S_ * HID_];
__device__ __nv_bfloat16 g_xlo[(size_t)S_ * HID_];
__device__ __nv_bfloat16 g_wqt_hi[(size_t)THREE_HID * HID_];  // Wqkv^T [N][K]
__device__ __nv_bfloat16 g_wqt_lo[(size_t)THREE_HID * HID_];
__device__ __nv_bfloat16 g_wpt_hi[(size_t)HID_ * HID_];       // Wproj^T [N][K]
__device__ __nv_bfloat16 g_wpt_lo[(size_t)HID_ * HID_];
__device__ __nv_bfloat16 g_ahi[(size_t)S_ * HID_];            // attn out hi/lo
__device__ __nv_bfloat16 g_alo[(size_t)S_ * HID_];
__device__ __nv_bfloat16 g_qhi[(size_t)H_ * S_ * D_];
__device__ __nv_bfloat16 g_qlo[(size_t)H_ * S_ * D_];
__device__ __nv_bfloat16 g_khi[(size_t)H_ * S_ * D_];
__device__ __nv_bfloat16 g_klo[(size_t)H_ * S_ * D_];
__device__ __nv_bfloat16 g_vhi[(size_t)H_ * S_ * D_];
__device__ __nv_bfloat16 g_vlo[(size_t)H_ * S_ * D_];

__device__ __forceinline__ uint32_t smem_u32(const void* p) {
    uint32_t a;
    asm("{ .reg .u64 t; cvta.to.shared.u64 t, %1; cvt.u32.u64 %0, t; }"
        : "=r"(a) : "l"(p));
    return a;
}
__device__ __forceinline__ uint32_t pk2(float lo, float hi) {
    uint32_t r;
    asm("cvt.rn.bf16x2.f32 %0, %1, %2;" : "=r"(r) : "f"(hi), "f"(lo));
    return r;
}
__device__ __forceinline__ float lo_of(uint32_t p) { return __uint_as_float(p << 16); }
__device__ __forceinline__ float hi_of(uint32_t p) { return __uint_as_float(p & 0xffff0000u); }

#define MMA4(cc, aa, b0, b1)                                                    \
    asm volatile("mma.sync.aligned.m16n8k16.row.col.f32.bf16.bf16.f32 "         \
                 "{%0,%1,%2,%3},{%4,%5,%6,%7},{%8,%9},{%0,%1,%2,%3};"           \
                 : "+f"((cc)[0]), "+f"((cc)[1]), "+f"((cc)[2]), "+f"((cc)[3])   \
                 : "r"((aa)[0]), "r"((aa)[1]), "r"((aa)[2]), "r"((aa)[3]),      \
                   "r"(b0), "r"(b1))
#define LDSM4(r, addr)                                                          \
    asm volatile("ldmatrix.sync.aligned.m8n8.x4.shared.b16 {%0,%1,%2,%3}, [%4];"\
                 : "=r"((r)[0]), "=r"((r)[1]), "=r"((r)[2]), "=r"((r)[3])       \
                 : "r"(addr))
#define LDSM4T(r, addr)                                                         \
    asm volatile("ldmatrix.sync.aligned.m8n8.x4.trans.shared.b16 {%0,%1,%2,%3}, [%4];" \
                 : "=r"((r)[0]), "=r"((r)[1]), "=r"((r)[2]), "=r"((r)[3])       \
                 : "r"(addr))
#define CPA16(dst, src)                                                         \
    asm volatile("cp.async.cg.shared.global [%0], [%1], 16;" :: "r"(dst), "l"(src))

// ---------------------------------------------------------------------------
// bf16-split conversion kernels (vectorized)
// ---------------------------------------------------------------------------
__global__ void split_rows(const float* __restrict__ in,
                           __nv_bfloat16* __restrict__ hi,
                           __nv_bfloat16* __restrict__ lo, int n4)
{
    int i = blockIdx.x * blockDim.x + threadIdx.x;
    if (i >= n4) return;
    float4 v = *(const float4*)(in + 4 * (size_t)i);
    uint32_t h01 = pk2(v.x, v.y);
    uint32_t h23 = pk2(v.z, v.w);
    uint32_t l01 = pk2(v.x - lo_of(h01), v.y - hi_of(h01));
    uint32_t l23 = pk2(v.z - lo_of(h23), v.w - hi_of(h23));
    uint2 hv; hv.x = h01; hv.y = h23;
    uint2 lv; lv.x = l01; lv.y = l23;
    *(uint2*)(hi + 4 * (size_t)i) = hv;
    *(uint2*)(lo + 4 * (size_t)i) = lv;
}

__global__ void split_t(const float* __restrict__ W,
                        __nv_bfloat16* __restrict__ hi,
                        __nv_bfloat16* __restrict__ lo, int K, int N)
{
    __shared__ float t[32][33];
    int n0 = blockIdx.x * 32, k0 = blockIdx.y * 32;
    int tx = threadIdx.x, ty = threadIdx.y;   // (32, 8)
#pragma unroll
    for (int i = 0; i < 32; i += 8)
        t[ty + i][tx] = W[(size_t)(k0 + ty + i) * N + n0 + tx];
    __syncthreads();
#pragma unroll
    for (int i = 0; i < 32; i += 8) {
        float v = t[tx][ty + i];
        __nv_bfloat16 h = __float2bfloat16(v);
        size_t o = (size_t)(n0 + ty + i) * K + k0 + tx;
        hi[o] = h;
        lo[o] = __float2bfloat16(v - __bfloat162float(h));
    }
}

// ---------------------------------------------------------------------------
// Small-CTA bf16-split GEMM: C = A @ B^T + bias.
// 64(M) x 128(N) tile, BK=32, 128 threads (4 warps, warp tile 32x64),
// double-buffered cp.async, 3 CTAs/SM.  3-term split.
// ---------------------------------------------------------------------------
#define AST 40
#define A64_BYTES (64 * AST * 2)           // 5120
#define B128_BYTES (128 * AST * 2)         // 10240
#define STAGE_SM (2 * A64_BYTES + 2 * B128_BYTES)   // 30720
#define GEMM_SM_SMEM_BYTES (2 * STAGE_SM)           // 61440

__global__ __launch_bounds__(128, 3) void mma_gemm_bias_sm(
    const __nv_bfloat16* __restrict__ Ahi, const __nv_bfloat16* __restrict__ Alo,
    const __nv_bfloat16* __restrict__ Bhi, const __nv_bfloat16* __restrict__ Blo,
    const float* __restrict__ bias, float* __restrict__ Cm,
    int M, int N, int K)
{
    extern __shared__ __nv_bfloat16 smb[];
    const uint32_t sb = smem_u32(smb);

    const int tid  = threadIdx.x;
    const int lane = tid & 31, warp = tid >> 5;   // 0..3
    const int warpM = warp & 1;
    const int warpN = warp >> 1;
    const int quad = lane >> 3, l8 = lane & 7;
    const int tileN = blockIdx.x, tileM = blockIdx.y;

    const __nv_bfloat16* gAh = Ahi + (size_t)(tileM * 64) * K;
    const __nv_bfloat16* gAl = Alo + (size_t)(tileM * 64) * K;
    const __nv_bfloat16* gBh = Bhi + (size_t)(tileN * 128) * K;
    const __nv_bfloat16* gBl = Blo + (size_t)(tileN * 128) * K;

    float c[2][8][4];
#pragma unroll
    for (int mi = 0; mi < 2; mi++)
#pragma unroll
        for (int nt = 0; nt < 8; nt++)
#pragma unroll
            for (int r = 0; r < 4; r++) c[mi][nt][r] = 0.f;

    const int nch = K >> 5;

    auto issue = [&](int ch, int buf) {
        const int k0 = ch * 32;
        const uint32_t base = sb + (uint32_t)(buf * STAGE_SM);
#pragma unroll
        for (int p = 0; p < 2; p++) {    // A: 64 rows x 4 segs
            int idx = tid + p * 128;
            int row = idx >> 2, seg = idx & 3;
            uint32_t so = (uint32_t)((row * AST + seg * 8) * 2);
            size_t go = (size_t)row * K + k0 + seg * 8;
            CPA16(base + so,             gAh + go);
            CPA16(base + A64_BYTES + so, gAl + go);
        }
#pragma unroll
        for (int p = 0; p < 4; p++) {    // B: 128 rows x 4 segs
            int idx = tid + p * 128;
            int row = idx >> 2, seg = idx & 3;
            uint32_t so = (uint32_t)((row * AST + seg * 8) * 2);
            size_t go = (size_t)row * K + k0 + seg * 8;
            CPA16(base + 2 * A64_BYTES + so,              gBh + go);
            CPA16(base + 2 * A64_BYTES + B128_BYTES + so, gBl + go);
        }
        asm volatile("cp.async.commit_group;" ::: "memory");
    };

    issue(0, 0);

    for (int ch = 0; ch < nch; ch++) {
        if (ch + 1 < nch) {
            issue(ch + 1, (ch + 1) & 1);
            asm volatile("cp.async.wait_group 1;" ::: "memory");
        } else {
            asm volatile("cp.async.wait_group 0;" ::: "memory");
        }
        __syncthreads();

        const uint32_t base = sb + (uint32_t)((ch & 1) * STAGE_SM);
        const uint32_t aHb = base;
        const uint32_t aLb = base + A64_BYTES;
        const uint32_t bHb = base + 2 * A64_BYTES;
        const uint32_t bLb = base + 2 * A64_BYTES + B128_BYTES;

#pragma unroll
        for (int s = 0; s < 2; s++) {
            uint32_t ah[2][4], al[2][4], bh[4][4], bl[4][4];
#pragma unroll
            for (int mi = 0; mi < 2; mi++) {
                int row = warpM * 32 + mi * 16 + (quad & 1) * 8 + l8;
                int ke  = s * 16 + (quad >> 1) * 8;
                LDSM4(ah[mi], aHb + (uint32_t)((row * AST + ke) * 2));
                LDSM4(al[mi], aLb + (uint32_t)((row * AST + ke) * 2));
            }
#pragma unroll
            for (int nj = 0; nj < 4; nj++) {
                int nrow = warpN * 64 + nj * 16 + (quad >> 1) * 8 + l8;
                int ke   = s * 16 + (quad & 1) * 8;
                LDSM4(bh[nj], bHb + (uint32_t)((nrow * AST + ke) * 2));
                LDSM4(bl[nj], bLb + (uint32_t)((nrow * AST + ke) * 2));
            }
#pragma unroll
            for (int mi = 0; mi < 2; mi++)
#pragma unroll
                for (int nt = 0; nt < 8; nt++) {
                    int nj = nt >> 1, hh = (nt & 1) * 2;
                    MMA4(c[mi][nt], ah[mi], bh[nj][hh], bh[nj][hh + 1]);
                }
#pragma unroll
            for (int mi = 0; mi < 2; mi++)
#pragma unroll
                for (int nt = 0; nt < 8; nt++) {
                    int nj = nt >> 1, hh = (nt & 1) * 2;
                    MMA4(c[mi][nt], ah[mi], bl[nj][hh], bl[nj][hh + 1]);
                }
#pragma unroll
            for (int mi = 0; mi < 2; mi++)
#pragma unroll
                for (int nt = 0; nt < 8; nt++) {
                    int nj = nt >> 1, hh = (nt & 1) * 2;
                    MMA4(c[mi][nt], al[mi], bh[nj][hh], bh[nj][hh + 1]);
                }
        }
        __syncthreads();
    }

    const int m0 = tileM * 64 + warpM * 32;
    const int n0 = tileN * 128 + warpN * 64;
    const int rq = lane >> 2, cq = (lane & 3) * 2;
#pragma unroll
    for (int mi = 0; mi < 2; mi++) {
#pragma unroll
        for (int nt = 0; nt < 8; nt++) {
            int col = n0 + nt * 8 + cq;
            float2 b2 = *(const float2*)(bias + col);
            int r0 = m0 + mi * 16 + rq;
            float2 o0, o1;
            o0.x = c[mi][nt][0] + b2.x; o0.y = c[mi][nt][1] + b2.y;
            o1.x = c[mi][nt][2] + b2.x; o1.y = c[mi][nt][3] + b2.y;
            *(float2*)(Cm + (size_t)r0 * N + col)       = o0;
            *(float2*)(Cm + (size_t)(r0 + 8) * N + col) = o1;
        }
    }
}

// ---------------------------------------------------------------------------
// RoPE + split (vectorized, 2 elems/thread), row-half via s0 offset.
// ---------------------------------------------------------------------------
__global__ void rope_split(const float* __restrict__ cosp,
                           const float* __restrict__ sinp, int s0, int nhalf)
{
    int i = blockIdx.x * blockDim.x + threadIdx.x;
    if (i >= nhalf) return;
    int s   = s0 + i / (HID_ / 2);
    int c2  = i - (s - s0) * (HID_ / 2);
    int col = c2 * 2;
    int h   = col / D_;
    int d   = col - h * D_;   // even; d and d+1 on the same side of 40

    const float* base = g_qkv + (size_t)s * THREE_HID;
    float2 qv = *(const float2*)(base + col);
    float2 kv = *(const float2*)(base + HID_ + col);
    float2 vv = *(const float2*)(base + 2 * HID_ + col);
    float2 cc = *(const float2*)(cosp + s * D_ + d);
    float2 sn = *(const float2*)(sinp + s * D_ + d);

    int off = (d < 40) ? (col + 40) : (col - 40);
    float sgn = (d < 40) ? -1.f : 1.f;
    float2 qr = *(const float2*)(base + off);
    float2 kr = *(const float2*)(base + HID_ + off);

    const float inv_scale = rsqrtf((float)D_);
    float qf0 = (qv.x * cc.x + sgn * qr.x * sn.x) * inv_scale;
    float qf1 = (qv.y * cc.y + sgn * qr.y * sn.y) * inv_scale;
    float kf0 = kv.x * cc.x + sgn * kr.x * sn.x;
    float kf1 = kv.y * cc.y + sgn * kr.y * sn.y;

    size_t o = (size_t)h * S_ * D_ + (size_t)s * D_ + d;
    uint32_t qh = pk2(qf0, qf1);
    *(uint32_t*)(g_qhi + o) = qh;
    *(uint32_t*)(g_qlo + o) = pk2(qf0 - lo_of(qh), qf1 - hi_of(qh));
    uint32_t kh = pk2(kf0, kf1);
    *(uint32_t*)(g_khi + o) = kh;
    *(uint32_t*)(g_klo + o) = pk2(kf0 - lo_of(kh), kf1 - hi_of(kh));
    uint32_t vh = pk2(vv.x, vv.y);
    *(uint32_t*)(g_vhi + o) = vh;
    *(uint32_t*)(g_vlo + o) = pk2(vv.x - lo_of(vh), vv.y - hi_of(vh));
}

// ---------------------------------------------------------------------------
// HMMA flash attention. 64 q-rows/CTA, 64k tiles, 4 warps, 2 CTAs/SM.
// Chunk-half via c0 offset.
// ---------------------------------------------------------------------------
#define ATT_STRIDE 88
#define Q_BYTES (64 * ATT_STRIDE * 2)     // 11264
#define T_BYTES (64 * ATT_STRIDE * 2)     // 11264
#define OFF_QH 0
#define OFF_QL Q_BYTES
#define OFF_KH (2 * Q_BYTES)
#define OFF_KL (2 * Q_BYTES + 2 * T_BYTES)
#define OFF_VH (2 * Q_BYTES + 4 * T_BYTES)
#define OFF_VL (2 * Q_BYTES + 6 * T_BYTES)
#define ATTN_SMEM_BYTES (2 * Q_BYTES + 8 * T_BYTES)   // 112640

__global__ __launch_bounds__(128, 2) void attn_mma(int c0)
{
    extern __shared__ char smc[];
    const uint32_t sb = smem_u32(smc);

    const int bx = blockIdx.x;
    const int qt = bx & 15;           // 16 q-tiles of 64 rows
    const int h  = (bx >> 4) & 15;
    const int c  = c0 + (bx >> 8);

    const int tid = threadIdx.x;
    const int lane = tid & 31, w = tid >> 5;   // w: 0..3
    const int quad = lane >> 3, l8 = lane & 7;

    const size_t hq = (size_t)h * S_ * D_ + (size_t)(c * L_ + qt * 64) * D_;
    const size_t hk = (size_t)h * S_ * D_ + (size_t)(c * L_) * D_;

    for (int i = tid; i < 640; i += 128) {
        int row = i / 10, seg = i - row * 10;
        uint32_t off = (uint32_t)(row * ATT_STRIDE + seg * 8) * 2;
        size_t g = hq + (size_t)row * 80 + seg * 8;
        CPA16(sb + OFF_QH + off, g_qhi + g);
        CPA16(sb + OFF_QL + off, g_qlo + g);
    }
    for (int i = tid; i < 640; i += 128) {
        int row = i / 10, seg = i - row * 10;
        uint32_t off = (uint32_t)(row * ATT_STRIDE + seg * 8) * 2;
        size_t g = hk + (size_t)row * 80 + seg * 8;
        CPA16(sb + OFF_KH + off, g_khi + g);
        CPA16(sb + OFF_KL + off, g_klo + g);
        CPA16(sb + OFF_VH + off, g_vhi + g);
        CPA16(sb + OFF_VL + off, g_vlo + g);
    }
    asm volatile("cp.async.commit_group;" ::: "memory");

    float m_a = -1e30f, m_b = -1e30f, l_a = 0.f, l_b = 0.f;
    float out[10][4];
#pragma unroll
    for (int vt = 0; vt < 10; vt++)
#pragma unroll
        for (int r = 0; r < 4; r++) out[vt][r] = 0.f;

    for (int t = 0; t < 16; t++) {
        if (t + 1 < 16) {
            const uint32_t s1 = ((t + 1) & 1) * T_BYTES;
            const size_t tb = hk + (size_t)(t + 1) * 64 * 80;
            for (int i = tid; i < 640; i += 128) {
                int row = i / 10, seg = i - row * 10;
                uint32_t off = (uint32_t)(row * ATT_STRIDE + seg * 8) * 2 + s1;
                size_t g = tb + (size_t)row * 80 + seg * 8;
                CPA16(sb + OFF_KH + off, g_khi + g);
                CPA16(sb + OFF_KL + off, g_klo + g);
                CPA16(sb + OFF_VH + off, g_vhi + g);
                CPA16(sb + OFF_VL + off, g_vlo + g);
            }
            asm volatile("cp.async.commit_group;" ::: "memory");
            asm volatile("cp.async.wait_group 1;" ::: "memory");
        } else {
            asm volatile("cp.async.wait_group 0;" ::: "memory");
        }
        __syncthreads();

        const uint32_t stg = (t & 1) * T_BYTES;
        const uint32_t KHs = sb + OFF_KH + stg;
        const uint32_t KLs = sb + OFF_KL + stg;
        const uint32_t VHs = sb + OFF_VH + stg;
        const uint32_t VLs = sb + OFF_VL + stg;

        float sc[8][4];
#pragma unroll
        for (int nt = 0; nt < 8; nt++)
#pragma unroll
            for (int r = 0; r < 4; r++) sc[nt][r] = 0.f;

        const int arow = w * 16 + (quad & 1) * 8 + l8;
#pragma unroll
        for (int kk = 0; kk < 5; kk++) {
            uint32_t ah[4], al[4], bh[4][4], bl[4][4];
            uint32_t aoff = (uint32_t)(arow * ATT_STRIDE + kk * 16 + (quad >> 1) * 8) * 2;
            LDSM4(ah, sb + OFF_QH + aoff);
            LDSM4(al, sb + OFF_QL + aoff);
#pragma unroll
            for (int nj = 0; nj < 4; nj++) {
                uint32_t boff = (uint32_t)((nj * 16 + (quad >> 1) * 8 + l8) * ATT_STRIDE
                                           + kk * 16 + (quad & 1) * 8) * 2;
                LDSM4(bh[nj], KHs + boff);
                LDSM4(bl[nj], KLs + boff);
            }
#pragma unroll
            for (int nj = 0; nj < 4; nj++) {
                MMA4(sc[2 * nj],     ah, bh[nj][0], bh[nj][1]);
                MMA4(sc[2 * nj + 1], ah, bh[nj][2], bh[nj][3]);
            }
#pragma unroll
            for (int nj = 0; nj < 4; nj++) {
                MMA4(sc[2 * nj],     ah, bl[nj][0], bl[nj][1]);
                MMA4(sc[2 * nj + 1], ah, bl[nj][2], bl[nj][3]);
            }
#pragma unroll
            for (int nj = 0; nj < 4; nj++) {
                MMA4(sc[2 * nj],     al, bh[nj][0], bh[nj][1]);
                MMA4(sc[2 * nj + 1], al, bh[nj][2], bh[nj][3]);
            }
        }

        float mxa = sc[0][0], mxb = sc[0][2];
#pragma unroll
        for (int nt = 0; nt < 8; nt++) {
            mxa = fmaxf(mxa, fmaxf(sc[nt][0], sc[nt][1]));
            mxb = fmaxf(mxb, fmaxf(sc[nt][2], sc[nt][3]));
        }
        mxa = fmaxf(mxa, __shfl_xor_sync(0xffffffffu, mxa, 1));
        mxa = fmaxf(mxa, __shfl_xor_sync(0xffffffffu, mxa, 2));
        mxb = fmaxf(mxb, __shfl_xor_sync(0xffffffffu, mxb, 1));
        mxb = fmaxf(mxb, __shfl_xor_sync(0xffffffffu, mxb, 2));
        float nma = fmaxf(m_a, mxa), nmb = fmaxf(m_b, mxb);
        float ca  = __expf(m_a - nma), cb = __expf(m_b - nmb);
        m_a = nma; m_b = nmb;

        float sa = 0.f, sbv = 0.f;
#pragma unroll
        for (int nt = 0; nt < 8; nt++) {
            sc[nt][0] = __expf(sc[nt][0] - m_a);
            sc[nt][1] = __expf(sc[nt][1] - m_a);
            sc[nt][2] = __expf(sc[nt][2] - m_b);
            sc[nt][3] = __expf(sc[nt][3] - m_b);
            sa  += sc[nt][0] + sc[nt][1];
            sbv += sc[nt][2] + sc[nt][3];
        }
        sa  += __shfl_xor_sync(0xffffffffu, sa, 1);
        sa  += __shfl_xor_sync(0xffffffffu, sa, 2);
        sbv += __shfl_xor_sync(0xffffffffu, sbv, 1);
        sbv += __shfl_xor_sync(0xffffffffu, sbv, 2);
        l_a = l_a * ca + sa;
        l_b = l_b * cb + sbv;

        uint32_t Ph[4][4], Pl[4][4];
#pragma unroll
        for (int kk = 0; kk < 4; kk++) {
#pragma unroll
            for (int half = 0; half < 2; half++) {
                int nt = 2 * kk + half;
                uint32_t h0 = pk2(sc[nt][0], sc[nt][1]);
                uint32_t h1 = pk2(sc[nt][2], sc[nt][3]);
                Ph[kk][2 * half + 0] = h0;
                Ph[kk][2 * half + 1] = h1;
                Pl[kk][2 * half + 0] = pk2(sc[nt][0] - lo_of(h0), sc[nt][1] - hi_of(h0));
                Pl[kk][2 * half + 1] = pk2(sc[nt][2] - lo_of(h1), sc[nt][3] - hi_of(h1));
            }
        }

#pragma unroll
        for (int vt = 0; vt < 10; vt++) {
            out[vt][0] *= ca; out[vt][1] *= ca;
            out[vt][2] *= cb; out[vt][3] *= cb;
        }

#pragma unroll
        for (int kk = 0; kk < 4; kk++) {
#pragma unroll
            for (int vj = 0; vj < 5; vj++) {
                uint32_t vhf[4], vlf[4];
                uint32_t voff = (uint32_t)((kk * 16 + (quad & 1) * 8 + l8) * ATT_STRIDE
                                           + vj * 16 + (quad >> 1) * 8) * 2;
                LDSM4T(vhf, VHs + voff);
                LDSM4T(vlf, VLs + voff);
                MMA4(out[2 * vj],     Ph[kk], vhf[0], vhf[1]);
                MMA4(out[2 * vj + 1], Ph[kk], vhf[2], vhf[3]);
                MMA4(out[2 * vj],     Ph[kk], vlf[0], vlf[1]);
                MMA4(out[2 * vj + 1], Ph[kk], vlf[2], vlf[3]);
                MMA4(out[2 * vj],     Pl[kk], vhf[0], vhf[1]);
                MMA4(out[2 * vj + 1], Pl[kk], vhf[2], vhf[3]);
            }
        }
        __syncthreads();
    }

    float ila = 1.f / l_a, ilb = 1.f / l_b;
    int ra = c * L_ + qt * 64 + w * 16 + (lane >> 2);
    int colb = h * D_ + (lane & 3) * 2;
#pragma unroll
    for (int vt = 0; vt < 10; vt++) {
        int col = colb + vt * 8;
        float v0 = out[vt][0] * ila, v1 = out[vt][1] * ila;
        uint32_t hp = pk2(v0, v1);
        uint32_t lp = pk2(v0 - lo_of(hp), v1 - hi_of(hp));
        *(uint32_t*)(g_ahi + (size_t)ra * HID_ + col) = hp;
        *(uint32_t*)(g_alo + (size_t)ra * HID_ + col) = lp;
        float v2 = out[vt][2] * ilb, v3 = out[vt][3] * ilb;
        hp = pk2(v2, v3);
        lp = pk2(v2 - lo_of(hp), v3 - hi_of(hp));
        *(uint32_t*)(g_ahi + (size_t)(ra + 8) * HID_ + col) = hp;
        *(uint32_t*)(g_alo + (size_t)(ra + 8) * HID_ + col) = lp;
    }
}

// ---------------------------------------------------------------------------
// Launch pipeline: two chunk-half chains on two streams.  Events are
// recorded BEFORE any wait on them (stream-capture legality).
// ---------------------------------------------------------------------------
#define HS (S_ / 2)   // 4096 rows per half

extern "C" void kernel_launch(void* const* d_in, const int* in_sizes, int n_in,
                              void* d_out, int out_size)
{
    const float* x     = (const float*)d_in[0];
    const float* cosp  = (const float*)d_in[1];
    const float* sinp  = (const float*)d_in[2];
    const float* Wqkv  = (const float*)d_in[3];
    const float* bqkv  = (const float*)d_in[4];
    const float* Wproj = (const float*)d_in[5];
    const float* bproj = (const float*)d_in[6];
    float* out = (float*)d_out;

    float* qkv_p;
    __nv_bfloat16 *xhi, *xlo, *wqh, *wql, *wph, *wpl, *ahi, *alo;
    cudaGetSymbolAddress((void**)&qkv_p, g_qkv);
    cudaGetSymbolAddress((void**)&xhi, g_xhi);
    cudaGetSymbolAddress((void**)&xlo, g_xlo);
    cudaGetSymbolAddress((void**)&wqh, g_wqt_hi);
    cudaGetSymbolAddress((void**)&wql, g_wqt_lo);
    cudaGetSymbolAddress((void**)&wph, g_wpt_hi);
    cudaGetSymbolAddress((void**)&wpl, g_wpt_lo);
    cudaGetSymbolAddress((void**)&ahi, g_ahi);
    cudaGetSymbolAddress((void**)&alo, g_alo);

    static int init_done = 0;
    static cudaStream_t s1, s2;
    static cudaEvent_t evA, evWq, evWp, evF1, evF2;
    if (!init_done) {
        cudaFuncSetAttribute(attn_mma,
                             cudaFuncAttributeMaxDynamicSharedMemorySize,
                             ATTN_SMEM_BYTES);
        cudaFuncSetAttribute(mma_gemm_bias_sm,
                             cudaFuncAttributeMaxDynamicSharedMemorySize,
                             GEMM_SM_SMEM_BYTES);
        cudaStreamCreateWithFlags(&s1, cudaStreamNonBlocking);
        cudaStreamCreateWithFlags(&s2, cudaStreamNonBlocking);
        cudaEventCreateWithFlags(&evA, cudaEventDisableTiming);
        cudaEventCreateWithFlags(&evWq, cudaEventDisableTiming);
        cudaEventCreateWithFlags(&evWp, cudaEventDisableTiming);
        cudaEventCreateWithFlags(&evF1, cudaEventDisableTiming);
        cudaEventCreateWithFlags(&evF2, cudaEventDisableTiming);
        init_done = 1;
    }

    // ---- fork from main ----
    cudaEventRecord(evA, 0);
    cudaStreamWaitEvent(s1, evA, 0);
    cudaStreamWaitEvent(s2, evA, 0);

    // ---- weight conversions first (events recorded before any wait) ----
    split_t<<<dim3(THREE_HID / 32, HID_ / 32), dim3(32, 8), 0, s1>>>(
        Wqkv, wqh, wql, HID_, THREE_HID);
    cudaEventRecord(evWq, s1);
    split_t<<<dim3(HID_ / 32, HID_ / 32), dim3(32, 8), 0, s2>>>(
        Wproj, wph, wpl, HID_, HID_);
    cudaEventRecord(evWp, s2);

    // ---- chain A (s1): half 0 = rows 0..HS-1, chunks 0..3 ----
    split_rows<<<(HS * HID_ / 4 + 255) / 256, 256, 0, s1>>>(
        x, xhi, xlo, HS * HID_ / 4);
    mma_gemm_bias_sm<<<dim3(THREE_HID / 128, HS / 64), 128, GEMM_SM_SMEM_BYTES, s1>>>(
        xhi, xlo, wqh, wql, bqkv, qkv_p, HS, THREE_HID, HID_);
    rope_split<<<(HS * HID_ / 2 + 255) / 256, 256, 0, s1>>>(cosp, sinp, 0, HS * HID_ / 2);
    attn_mma<<<(C_ / 2) * H_ * (L_ / 64), 128, ATTN_SMEM_BYTES, s1>>>(0);
    cudaStreamWaitEvent(s1, evWp, 0);
    mma_gemm_bias_sm<<<dim3(HID_ / 128, HS / 64), 128, GEMM_SM_SMEM_BYTES, s1>>>(
        ahi, alo, wph, wpl, bproj, out, HS, HID_, HID_);
    cudaEventRecord(evF1, s1);

    // ---- chain B (s2): half 1 = rows HS..S-1, chunks 4..7 ----
    split_rows<<<(HS * HID_ / 4 + 255) / 256, 256, 0, s2>>>(
        x + (size_t)HS * HID_, xhi + (size_t)HS * HID_, xlo + (size_t)HS * HID_,
        HS * HID_ / 4);
    cudaStreamWaitEvent(s2, evWq, 0);
    mma_gemm_bias_sm<<<dim3(THREE_HID / 128, HS / 64), 128, GEMM_SM_SMEM_BYTES, s2>>>(
        xhi + (size_t)HS * HID_, xlo + (size_t)HS * HID_, wqh, wql, bqkv,
        qkv_p + (size_t)HS * THREE_HID, HS, THREE_HID, HID_);
    rope_split<<<(HS * HID_ / 2 + 255) / 256, 256, 0, s2>>>(cosp, sinp, HS, HS * HID_ / 2);
    attn_mma<<<(C_ / 2) * H_ * (L_ / 64), 128, ATTN_SMEM_BYTES, s2>>>(C_ / 2);
    mma_gemm_bias_sm<<<dim3(HID_ / 128, HS / 64), 128, GEMM_SM_SMEM_BYTES, s2>>>(
        ahi + (size_t)HS * HID_, alo + (size_t)HS * HID_, wph, wpl, bproj,
        out + (size_t)HS * HID_, HS, HID_, HID_);
    cudaEventRecord(evF2, s2);

    // ---- join to main ----
    cudaStreamWaitEvent(0, evF1, 0);
    cudaStreamWaitEvent(0, evF2, 0);
}